// round 13
// baseline (speedup 1.0000x reference)
#include <cuda_runtime.h>
#include <cuda_bf16.h>
#include <math.h>
#include <cstdint>

#define NB 8
#define CI 256
#define CM 192
#define CO 128
#define LV 512
#define HH 128
#define WW 128
#define OH 256
#define OW 256

// ===================== warp-MMA helpers (base ISA, sm_80+) =================
__device__ __forceinline__ uint32_t smem_u32(const void* p) {
    uint32_t a;
    asm("{ .reg .u64 t; cvta.to.shared.u64 t, %1; cvt.u32.u64 %0, t; }"
        : "=r"(a) : "l"(p));
    return a;
}
__device__ __forceinline__ void ldsm_x4(uint32_t* r, uint32_t addr) {
    asm volatile("ldmatrix.sync.aligned.m8n8.x4.shared.b16 {%0,%1,%2,%3}, [%4];"
                 : "=r"(r[0]), "=r"(r[1]), "=r"(r[2]), "=r"(r[3]) : "r"(addr));
}
__device__ __forceinline__ void mma16816(float* d, const uint32_t* a,
                                         uint32_t b0, uint32_t b1) {
    asm volatile(
        "mma.sync.aligned.m16n8k16.row.col.f32.bf16.bf16.f32 "
        "{%0,%1,%2,%3}, {%4,%5,%6,%7}, {%8,%9}, {%0,%1,%2,%3};"
        : "+f"(d[0]), "+f"(d[1]), "+f"(d[2]), "+f"(d[3])
        : "r"(a[0]), "r"(a[1]), "r"(a[2]), "r"(a[3]), "r"(b0), "r"(b1));
}
__device__ __forceinline__ void cpasync16(uint32_t dst, const void* src) {
    asm volatile("cp.async.ca.shared.global [%0], [%1], 16;"
                 :: "r"(dst), "l"(src) : "memory");
}
__device__ __forceinline__ void cpasync16p(uint32_t dst, const void* src, uint32_t sz) {
    asm volatile("cp.async.ca.shared.global [%0], [%1], 16, %2;"
                 :: "r"(dst), "l"(src), "r"(sz) : "memory");
}
#define CP_COMMIT() asm volatile("cp.async.commit_group;" ::: "memory")
#define CP_WAIT2() asm volatile("cp.async.wait_group 2;" ::: "memory")
#define CP_WAIT0() asm volatile("cp.async.wait_group 0;" ::: "memory")

// truncation split of two f32 -> (hi-pair, lo-pair) packed bf16x2
__device__ __forceinline__ void split2(float h0, float h1, uint32_t& hiP, uint32_t& loP) {
    uint32_t b0 = __float_as_uint(h0), b1 = __float_as_uint(h1);
    hiP = __byte_perm(b0, b1, 0x7632);
    float r0 = h0 - __uint_as_float(b0 & 0xFFFF0000u);
    float r1 = h1 - __uint_as_float(b1 & 0xFFFF0000u);
    asm("cvt.rn.bf16x2.f32 %0, %1, %2;" : "=r"(loP) : "f"(r1), "f"(r0));
}

// ===================== device globals ======================================
__device__ __align__(16) __nv_bfloat16 g_xsp[(size_t)NB * 8 * HH * WW * 64];
__device__ __align__(16) __nv_bfloat16 g_hs[(size_t)NB * 6 * OH * OW * 64];
__device__ __align__(16) __nv_bfloat16 g_wbs[6 * 9 * CO * 64];
__device__ __align__(16) __nv_bfloat16 g_wbs_up[9 * 8 * CM * 64];
__device__ float g_wsq_up[CM * CI];
__device__ float g_wsq_cv[CO * CM];
__device__ float g_s_up[NB * CI];
__device__ float g_s_cv[NB * CM];
__device__ float g_s_rgb[NB * CO];

__device__ __constant__ int AKo[6] = {0, 16, 32, 48, 0, 16};
__device__ __constant__ int BKo[6] = {0, 16, 0, 16, 32, 48};

// ---------------------------------------------------------------------------
__global__ void k_prep_w(const float* __restrict__ w_up,
                         const float* __restrict__ w_conv) {
    int idx = blockIdx.x * 256 + threadIdx.x;
    if (idx < CM * CI) {
        int o = idx / CI, i = idx % CI;
        const float* p = w_up + (i * CM + o) * 9;
        float acc = 0.f;
#pragma unroll
        for (int tt = 0; tt < 9; tt++) acc = fmaf(p[tt], p[tt], acc);
        g_wsq_up[idx] = acc;
    }
    if (idx < CO * CM) {
        int o = idx / CM, i = idx % CM;
        const float* p = w_conv + (o * CM + i) * 9;
        float acc = 0.f;
#pragma unroll
        for (int tt = 0; tt < 9; tt++) acc = fmaf(p[tt], p[tt], acc);
        g_wsq_cv[idx] = acc;
    }
    if (idx < 6 * 9 * CO * 64) {
        int k = idx % 64;
        int oc = (idx / 64) % CO;
        int t = (idx / (64 * CO)) % 9;
        int c = idx / (64 * CO * 9);
        int ic = c * 32 + (k & 31);
        float w = w_conv[(oc * CM + ic) * 9 + t];
        __nv_bfloat16 hi = __float2bfloat16(w);
        g_wbs[idx] = (k < 32) ? hi : __float2bfloat16(w - __bfloat162float(hi));
    }
    if (idx < 9 * 8 * CM * 64) {
        int k = idx % 64;
        int oc = (idx / 64) % CM;
        int c = (idx / (64 * CM)) % 8;
        int t = idx / (64 * CM * 8);
        int ic = c * 32 + (k & 31);
        float w = w_up[(ic * CM + oc) * 9 + t];
        __nv_bfloat16 hi = __float2bfloat16(w);
        g_wbs_up[idx] = (k < 32) ? hi : __float2bfloat16(w - __bfloat162float(hi));
    }
}

// ---------------------------------------------------------------------------
__global__ void k_style_all(const float* __restrict__ v,
                            const float* __restrict__ sw_up, const float* __restrict__ sb_up,
                            const float* __restrict__ sw_cv, const float* __restrict__ sb_cv,
                            const float* __restrict__ sw_rgb, const float* __restrict__ sb_rgb) {
    int warp = threadIdx.x >> 5, lane = threadIdx.x & 31;
    int cg = blockIdx.x * 8 + warp;
    int n = blockIdx.y;
    const float *sw, *sb;
    float* dst;
    int c;
    if (cg < 256)      { sw = sw_up;  sb = sb_up;  dst = g_s_up  + n * CI; c = cg; }
    else if (cg < 448) { sw = sw_cv;  sb = sb_cv;  dst = g_s_cv  + n * CM; c = cg - 256; }
    else               { sw = sw_rgb; sb = sb_rgb; dst = g_s_rgb + n * CO; c = cg - 448; }
    const float* vp = v + n * LV;
    const float* wp = sw + c * LV;
    float acc = 0.f;
#pragma unroll
    for (int l = lane; l < LV; l += 32) acc = fmaf(vp[l], wp[l], acc);
#pragma unroll
    for (int s = 16; s > 0; s >>= 1) acc += __shfl_xor_sync(0xFFFFFFFF, acc, s);
    if (lane == 0) dst[c] = acc + sb[c] + 1.0f;
}

// ---------------------------------------------------------------------------
__global__ void k_xsplit(const float* __restrict__ x) {
    __shared__ float sm[32][129];
    int py = blockIdx.x, c = blockIdx.y, n = blockIdx.z;
    int tid = threadIdx.x;
    for (int e = tid; e < 4096; e += 256) {
        int ic = e >> 7, px = e & 127;
        sm[ic][px] = x[(((size_t)n * CI + c * 32 + ic) << 14) + (py << 7) + px] *
                     g_s_up[n * CI + c * 32 + ic];
    }
    __syncthreads();
    int px = tid >> 1, hf = tid & 1;
    uint32_t hi[8], lo[8];
#pragma unroll
    for (int j = 0; j < 8; j++) {
        int p = hf * 8 + j;
        split2(sm[2 * p][px], sm[2 * p + 1][px], hi[j], lo[j]);
    }
    uint4* d4 = (uint4*)((uint32_t*)g_xsp +
                         ((size_t)(n * 8 + c) * 16384 + py * 128 + px) * 32);
    d4[hf * 2 + 0] = make_uint4(hi[0], hi[1], hi[2], hi[3]);
    d4[hf * 2 + 1] = make_uint4(hi[4], hi[5], hi[6], hi[7]);
    d4[4 + hf * 2 + 0] = make_uint4(lo[0], lo[1], lo[2], lo[3]);
    d4[4 + hf * 2 + 1] = make_uint4(lo[4], lo[5], lo[6], lo[7]);
}

// ---------------------------------------------------------------------------
// Upconv: parity-decomposed implicit GEMM, 512 thr, 4m x 4n (tile 32x48).
// A prefetch SLICED per tap (small commit groups -> no far-future blocking).
// ---------------------------------------------------------------------------
#define U_ABUF (153 * 144)
#define U_BBUF (192 * 144)
#define U_B0   (3 * U_ABUF)
#define U_ISG  (3 * U_ABUF + 3 * U_BBUF)
#define U_SMEM (U_ISG + CM * 4)
#define U_EPIP 200

__global__ __launch_bounds__(512, 1) void k_upconv_mma(
    const float* __restrict__ noise1, const float* __restrict__ b_up,
    const float* __restrict__ ns1p) {
    extern __shared__ __align__(16) char smem[];
    uint32_t sbase = smem_u32(smem);
    float* isg = (float*)(smem + U_ISG);

    int tid = threadIdx.x;
    int wid = tid >> 5, lane = tid & 31;
    int wm = wid & 3, wn = wid >> 2;
    int zc = blockIdx.z;
    int n = zc >> 2, cls = zc & 3;
    int y0 = blockIdx.y * 8, x0 = blockIdx.x * 16;

    int nt, ntsh, tapid[4], pixoff[4];
    if (cls == 0) {
        nt = 1; ntsh = 0;
        tapid[0] = 4; pixoff[0] = 0;
    } else if (cls == 1) {
        nt = 2; ntsh = 1;
        tapid[0] = 3; pixoff[0] = 1;
        tapid[1] = 5; pixoff[1] = 0;
    } else if (cls == 2) {
        nt = 2; ntsh = 1;
        tapid[0] = 1; pixoff[0] = 17;
        tapid[1] = 7; pixoff[1] = 0;
    } else {
        nt = 4; ntsh = 2;
        tapid[0] = 0; pixoff[0] = 18;
        tapid[1] = 2; pixoff[1] = 17;
        tapid[2] = 6; pixoff[2] = 1;
        tapid[3] = 8; pixoff[3] = 0;
    }
    const int NIT = nt * 8;
    const int asz = 1224 >> ntsh;      // A ops per slice

    int rowsel = lane & 15, ksel = lane >> 4;

    auto issueAr = [&](int cc, int lo, int hi2) {
        const char* asrc = (const char*)g_xsp + ((size_t)(n * 8 + cc) * 16384) * 128;
        uint32_t abuf = sbase + (cc % 3) * U_ABUF;
        for (int e = lo + tid; e < hi2; e += 512) {
            int pix = e >> 3, q = e & 7;
            int ry = pix / 17, rx = pix % 17;
            int gy = y0 + ry, gx = x0 + rx;
            uint32_t ok = (gy < HH && gx < WW) ? 16u : 0u;
            int gyc = gy < HH - 1 ? gy : HH - 1;
            int gxc = gx < WW - 1 ? gx : WW - 1;
            cpasync16p(abuf + pix * 144 + q * 16,
                       asrc + ((size_t)gyc * 128 + gxc) * 128 + q * 16, ok);
        }
    };
    auto issueB = [&](int it2) {
        int c2 = it2 >> ntsh, ti2 = it2 & (nt - 1);
        const char* bsrc = (const char*)g_wbs_up + (size_t)(tapid[ti2] * 8 + c2) * 24576;
        uint32_t bbuf = sbase + U_B0 + (it2 % 3) * U_BBUF;
#pragma unroll
        for (int i = 0; i < 3; i++) {
            int e = tid + i * 512;
            int row = e >> 3, q = e & 7;
            cpasync16(bbuf + row * 144 + q * 16, bsrc + row * 128 + q * 16);
        }
    };

    float acc[2][6][4];
#pragma unroll
    for (int mi = 0; mi < 2; mi++)
#pragma unroll
        for (int ni = 0; ni < 6; ni++)
#pragma unroll
            for (int q = 0; q < 4; q++) acc[mi][ni][q] = 0.f;

    issueAr(0, 0, 1224); CP_COMMIT();
    issueB(0); CP_COMMIT();
    issueAr(1, 0, 1224); CP_COMMIT();
    issueB(1); CP_COMMIT();

    // isg_up in-kernel (overlaps prologue cp.async)
    {
        const float* s = g_s_up + n * CI;
#pragma unroll
        for (int j = 0; j < 12; j++) {
            int o = wid * 12 + j;
            float a = 0.f;
            for (int i = lane; i < CI; i += 32) {
                float sv = s[i];
                a = fmaf(sv * sv, g_wsq_up[o * CI + i], a);
            }
#pragma unroll
            for (int sh = 16; sh > 0; sh >>= 1) a += __shfl_xor_sync(0xFFFFFFFF, a, sh);
            if (lane == 0) isg[o] = 1.0f / sqrtf(a + 1e-8f);
        }
    }

    for (int it = 0; it < NIT; it++) {
        int c = it >> ntsh, ti = it & (nt - 1);
        CP_WAIT2();
        __syncthreads();

        if (c + 2 < 8) issueAr(c + 2, ti * asz, (ti + 1) * asz);
        CP_COMMIT();
        if (it + 2 < NIT) issueB(it + 2);
        CP_COMMIT();

        uint32_t sA = sbase + (c % 3) * U_ABUF;
        uint32_t sB = sbase + U_B0 + (it % 3) * U_BBUF;
        int ap0 = ((wm * 2 + 0) * 17 + rowsel + pixoff[ti]) * 144;
        int ap1 = ((wm * 2 + 1) * 17 + rowsel + pixoff[ti]) * 144;
#pragma unroll
        for (int kk = 0; kk < 6; kk++) {
            int akoff = (AKo[kk] + ksel * 8) * 2;
            int bkoff = (BKo[kk] + ksel * 8) * 2;
            uint32_t ar[2][4];
            ldsm_x4(ar[0], sA + ap0 + akoff);
            ldsm_x4(ar[1], sA + ap1 + akoff);
            uint32_t br[3][4];
#pragma unroll
            for (int nj = 0; nj < 3; nj++)
                ldsm_x4(br[nj], sB + (wn * 48 + nj * 16 + rowsel) * 144 + bkoff);
#pragma unroll
            for (int mi = 0; mi < 2; mi++)
#pragma unroll
                for (int ni = 0; ni < 6; ni++) {
                    int nj = ni >> 1, pr = ni & 1;
                    mma16816(acc[mi][ni], ar[mi], br[nj][pr], br[nj][pr + 2]);
                }
        }
        __syncthreads();
    }

    CP_WAIT0();
    __syncthreads();

    float* smf = (float*)smem;
#pragma unroll
    for (int mi = 0; mi < 2; mi++)
#pragma unroll
        for (int ni = 0; ni < 6; ni++) {
            int m = wm * 32 + mi * 16 + (lane >> 2);
            int col = wn * 48 + ni * 8 + (lane & 3) * 2;
            smf[m * U_EPIP + col] = acc[mi][ni][0];
            smf[m * U_EPIP + col + 1] = acc[mi][ni][1];
            smf[(m + 8) * U_EPIP + col] = acc[mi][ni][2];
            smf[(m + 8) * U_EPIP + col + 1] = acc[mi][ni][3];
        }
    __syncthreads();

    {
        int px = tid & 127;
        int ocl = tid >> 7;
        int my = px >> 4, mx = px & 15;
        int oy = 2 * (y0 + my) + (cls >> 1);
        int ox = 2 * (x0 + mx) + (cls & 1);
        float nz = (*ns1p) * noise1[(size_t)n * OH * OW + oy * OW + ox];
        const float* scv = g_s_cv + n * CM;
#pragma unroll 4
        for (int ob = 0; ob < 48; ob++) {
            int oc = ob * 4 + ocl;
            float d = smf[px * U_EPIP + oc];
            float val = fmaf(d, isg[oc], b_up[oc]) + nz;
            val = (val > 0.f ? val : 0.2f * val) * scv[oc];
            smf[px * U_EPIP + oc] = val;
        }
    }
    __syncthreads();

    {
        uint32_t* gbase = (uint32_t*)g_hs + (size_t)n * 6 * 65536 * 32;
        for (int e = tid; e < 6144; e += 512) {
            int q = e & 7;
            int pxc = e >> 3;
            int px = pxc & 127;
            int cc = pxc >> 7;
            int my = px >> 4, mx = px & 15;
            int pxg = (2 * (y0 + my) + (cls >> 1)) * OW + 2 * (x0 + mx) + (cls & 1);
            int r = q >> 2;
            int pp0 = (q & 3) << 2;
            const float* sp = smf + px * U_EPIP + cc * 32 + 2 * pp0;
            uint32_t w[4];
#pragma unroll
            for (int j = 0; j < 4; j++) {
                uint32_t hiP, loP;
                split2(sp[2 * j], sp[2 * j + 1], hiP, loP);
                w[j] = (r == 1) ? loP : hiP;
            }
            *(uint4*)(gbase + ((size_t)cc * 65536 + pxg) * 32 + q * 4) =
                make_uint4(w[0], w[1], w[2], w[3]);
        }
    }
}

// ---------------------------------------------------------------------------
// Conv2 + to-RGB fused: M=256 px (16x16), 512 thr, 4m x 4n (tile 64x32).
// A prefetch SLICED per tap (1/9 chunk each commit).
// ---------------------------------------------------------------------------
#define C_ABUF (324 * 144)
#define C_BBUF (128 * 144)
#define C_B0   (3 * C_ABUF)
#define C_CF   (C_B0 + 3 * C_BBUF)
#define C_ISG  (C_CF + 3 * CO * 4)
#define C_SMEM (C_ISG + CO * 4)
#define EPIP 133

__global__ __launch_bounds__(512, 1) void k_conv2_mma(
    const float* __restrict__ noise2, const float* __restrict__ b_conv,
    const float* __restrict__ ns2p, const float* __restrict__ y,
    const float* __restrict__ w_rgb, const float* __restrict__ b_rgb,
    float* __restrict__ out, float* __restrict__ yout) {
    extern __shared__ __align__(16) char smem[];
    uint32_t sbase = smem_u32(smem);
    float* cf = (float*)(smem + C_CF);
    float* isg = (float*)(smem + C_ISG);

    int tid = threadIdx.x;
    int wid = tid >> 5, lane = tid & 31;
    int wm = wid & 3, wn = wid >> 2;
    int n = blockIdx.z;
    int y0 = blockIdx.y * 16, x0 = blockIdx.x * 16;

    int rowsel = lane & 15, ksel = lane >> 4;

    auto issueAr = [&](int cc, int lo, int hi2) {
        const char* asrc = (const char*)g_hs + ((size_t)(n * 6 + cc) * 65536) * 128;
        uint32_t abuf = sbase + (cc % 3) * C_ABUF;
        for (int e = lo + tid; e < hi2; e += 512) {
            int pix = e >> 3, q = e & 7;
            int ry = pix / 18, rx = pix % 18;
            int gy = y0 - 1 + ry, gx = x0 - 1 + rx;
            uint32_t ok = ((unsigned)gy < (unsigned)OH && (unsigned)gx < (unsigned)OW)
                              ? 16u : 0u;
            int gyc = gy < 0 ? 0 : (gy > OH - 1 ? OH - 1 : gy);
            int gxc = gx < 0 ? 0 : (gx > OW - 1 ? OW - 1 : gx);
            cpasync16p(abuf + pix * 144 + q * 16,
                       asrc + ((size_t)gyc * 256 + gxc) * 128 + q * 16, ok);
        }
    };
    auto issueB = [&](int it2) {
        const char* bsrc = (const char*)g_wbs + (size_t)it2 * 16384;
        uint32_t bbuf = sbase + C_B0 + (it2 % 3) * C_BBUF;
#pragma unroll
        for (int i = 0; i < 2; i++) {
            int e = tid + i * 512;
            int row = e >> 3, q = e & 7;
            cpasync16(bbuf + row * 144 + q * 16, bsrc + row * 128 + q * 16);
        }
    };

    float acc[4][4][4];
#pragma unroll
    for (int mi = 0; mi < 4; mi++)
#pragma unroll
        for (int ni = 0; ni < 4; ni++)
#pragma unroll
            for (int q = 0; q < 4; q++) acc[mi][ni][q] = 0.f;

    issueAr(0, 0, 2592); CP_COMMIT();
    issueB(0); CP_COMMIT();
    issueAr(1, 0, 2592); CP_COMMIT();
    issueB(1); CP_COMMIT();

    if (tid < CO) {
        float s = g_s_rgb[n * CO + tid];
#pragma unroll
        for (int c = 0; c < 3; c++) cf[c * CO + tid] = w_rgb[c * CO + tid] * s;
    }
    {
        const float* s = g_s_cv + n * CM;
#pragma unroll
        for (int j = 0; j < 8; j++) {
            int o = wid * 8 + j;
            float a = 0.f;
            for (int i = lane; i < CM; i += 32) {
                float sv = s[i];
                a = fmaf(sv * sv, g_wsq_cv[o * CM + i], a);
            }
#pragma unroll
            for (int sh = 16; sh > 0; sh >>= 1) a += __shfl_xor_sync(0xFFFFFFFF, a, sh);
            if (lane == 0) isg[o] = 1.0f / sqrtf(a + 1e-8f);
        }
    }

    int c = 0, t = 0;
    for (int it = 0; it < 54; it++) {
        CP_WAIT2();
        __syncthreads();

        if (c + 2 < 6) issueAr(c + 2, t * 288, (t + 1) * 288);
        CP_COMMIT();
        if (it + 2 < 54) issueB(it + 2);
        CP_COMMIT();

        uint32_t sA = sbase + (c % 3) * C_ABUF;
        uint32_t sB = sbase + C_B0 + (it % 3) * C_BBUF;
        int ky = t / 3, kx = t % 3;
        int ap[4];
#pragma unroll
        for (int mi = 0; mi < 4; mi++)
            ap[mi] = (((wm * 4 + mi) + ky) * 18 + kx + rowsel) * 144;
#pragma unroll
        for (int kk = 0; kk < 6; kk++) {
            int akoff = (AKo[kk] + ksel * 8) * 2;
            int bkoff = (BKo[kk] + ksel * 8) * 2;
            uint32_t ar[4][4];
#pragma unroll
            for (int mi = 0; mi < 4; mi++)
                ldsm_x4(ar[mi], sA + ap[mi] + akoff);
            uint32_t br[2][4];
#pragma unroll
            for (int nj = 0; nj < 2; nj++)
                ldsm_x4(br[nj], sB + (wn * 32 + nj * 16 + rowsel) * 144 + bkoff);
#pragma unroll
            for (int mi = 0; mi < 4; mi++)
#pragma unroll
                for (int ni = 0; ni < 4; ni++) {
                    int nj = ni >> 1, pr = ni & 1;
                    mma16816(acc[mi][ni], ar[mi], br[nj][pr], br[nj][pr + 2]);
                }
        }
        __syncthreads();
        if (++t == 9) { t = 0; c++; }
    }

    CP_WAIT0();
    __syncthreads();

    float* smf = (float*)smem;
#pragma unroll
    for (int mi = 0; mi < 4; mi++)
#pragma unroll
        for (int ni = 0; ni < 4; ni++) {
            int m = wm * 64 + mi * 16 + (lane >> 2);
            int col = wn * 32 + ni * 8 + (lane & 3) * 2;
            smf[m * EPIP + col] = acc[mi][ni][0];
            smf[m * EPIP + col + 1] = acc[mi][ni][1];
            smf[(m + 8) * EPIP + col] = acc[mi][ni][2];
            smf[(m + 8) * EPIP + col + 1] = acc[mi][ni][3];
        }
    __syncthreads();

    {
        int px = tid & 255;
        int ocl = tid >> 8;
        int my = px >> 4, mx = px & 15;
        int yy = y0 + my, xx = x0 + mx;
        float nz = (*ns2p) * noise2[(n * OH + yy) * OW + xx];
#pragma unroll 4
        for (int ob = 0; ob < 64; ob++) {
            int oc = ob * 2 + ocl;
            float d = smf[px * EPIP + oc];
            float val = fmaf(d, isg[oc], b_conv[oc]) + nz;
            val = val > 0.f ? val : 0.2f * val;
            smf[px * EPIP + oc] = val;
            out[(((size_t)n * CO + oc) * OH + yy) * OW + xx] = val;
        }
    }
    __syncthreads();

    if (tid < 256) {
        int px = tid;
        int my = px >> 4, mx = px & 15;
        int oy = y0 + my, ox = x0 + mx;
        float a0 = b_rgb[0], a1 = b_rgb[1], a2 = b_rgb[2];
        const float* sp = smf + px * EPIP;
#pragma unroll 4
        for (int oc = 0; oc < CO; oc++) {
            float hv = sp[oc];
            a0 = fmaf(hv, cf[oc], a0);
            a1 = fmaf(hv, cf[CO + oc], a1);
            a2 = fmaf(hv, cf[2 * CO + oc], a2);
        }
        a0 = a0 > 0.f ? a0 : 0.2f * a0;
        a1 = a1 > 0.f ? a1 : 0.2f * a1;
        a2 = a2 > 0.f ? a2 : 0.2f * a2;
        float rr[3] = {a0, a1, a2};

        float fy = 0.5f * oy - 0.25f;
        int iyf = (int)floorf(fy);
        float wy = fy - (float)iyf;
        int iy0 = iyf < 0 ? 0 : iyf;
        int iy1 = (iyf + 1) > (HH - 1) ? (HH - 1) : (iyf + 1);
        float fx = 0.5f * ox - 0.25f;
        int ixf = (int)floorf(fx);
        float wx = fx - (float)ixf;
        int ix0 = ixf < 0 ? 0 : ixf;
        int ix1 = (ixf + 1) > (WW - 1) ? (WW - 1) : (ixf + 1);

#pragma unroll
        for (int ch = 0; ch < 3; ch++) {
            const float* yp = y + ((size_t)(n * 3 + ch) * HH) * WW;
            float v00 = yp[iy0 * WW + ix0], v01 = yp[iy0 * WW + ix1];
            float v10 = yp[iy1 * WW + ix0], v11 = yp[iy1 * WW + ix1];
            float vt = v00 + (v01 - v00) * wx;
            float vb = v10 + (v11 - v10) * wx;
            float val = vt + (vb - vt) * wy;
            yout[(((size_t)n * 3 + ch) * OH + oy) * OW + ox] = val + rr[ch];
        }
    }
}

// ---------------------------------------------------------------------------
extern "C" void kernel_launch(void* const* d_in, const int* in_sizes, int n_in,
                              void* d_out, int out_size) {
    const float* x       = (const float*)d_in[0];
    const float* v       = (const float*)d_in[1];
    const float* y       = (const float*)d_in[2];
    const float* noise1  = (const float*)d_in[3];
    const float* noise2  = (const float*)d_in[4];
    const float* w_up    = (const float*)d_in[5];
    const float* b_up    = (const float*)d_in[6];
    const float* sw_up   = (const float*)d_in[7];
    const float* sb_up   = (const float*)d_in[8];
    const float* w_conv  = (const float*)d_in[9];
    const float* b_conv  = (const float*)d_in[10];
    const float* sw_conv = (const float*)d_in[11];
    const float* sb_conv = (const float*)d_in[12];
    const float* w_rgb   = (const float*)d_in[13];
    const float* b_rgb   = (const float*)d_in[14];
    const float* sw_rgb  = (const float*)d_in[15];
    const float* sb_rgb  = (const float*)d_in[16];
    const float* ns1     = (const float*)d_in[17];
    const float* ns2     = (const float*)d_in[18];
    float* out = (float*)d_out;

    (void)in_sizes; (void)n_in; (void)out_size;

    k_prep_w<<<(9 * 8 * CM * 64 + 255) / 256, 256>>>(w_up, w_conv);

    dim3 gst(72, NB);
    k_style_all<<<gst, 256>>>(v, sw_up, sb_up, sw_conv, sb_conv, sw_rgb, sb_rgb);

    dim3 gxs(128, 8, NB);
    k_xsplit<<<gxs, 256>>>(x);

    cudaFuncSetAttribute(k_upconv_mma, cudaFuncAttributeMaxDynamicSharedMemorySize,
                         U_SMEM);
    dim3 gup(8, 16, NB * 4);
    k_upconv_mma<<<gup, 512, U_SMEM>>>(noise1, b_up, ns1);

    cudaFuncSetAttribute(k_conv2_mma, cudaFuncAttributeMaxDynamicSharedMemorySize,
                         C_SMEM);
    dim3 gcv(16, 16, NB);
    k_conv2_mma<<<gcv, 512, C_SMEM>>>(noise2, b_conv, ns2, y, w_rgb, b_rgb,
                                      out, out + (size_t)NB * CO * OH * OW);
}

// round 14
// speedup vs baseline: 1.4522x; 1.4522x over previous
#include <cuda_runtime.h>
#include <cuda_bf16.h>
#include <math.h>
#include <cstdint>

#define NB 8
#define CI 256
#define CM 192
#define CO 128
#define LV 512
#define HH 128
#define WW 128
#define OH 256
#define OW 256

// ===================== warp-MMA helpers (base ISA, sm_80+) =================
__device__ __forceinline__ uint32_t smem_u32(const void* p) {
    uint32_t a;
    asm("{ .reg .u64 t; cvta.to.shared.u64 t, %1; cvt.u32.u64 %0, t; }"
        : "=r"(a) : "l"(p));
    return a;
}
__device__ __forceinline__ void ldsm_x4(uint32_t* r, uint32_t addr) {
    asm volatile("ldmatrix.sync.aligned.m8n8.x4.shared.b16 {%0,%1,%2,%3}, [%4];"
                 : "=r"(r[0]), "=r"(r[1]), "=r"(r[2]), "=r"(r[3]) : "r"(addr));
}
__device__ __forceinline__ void mma16816(float* d, const uint32_t* a,
                                         uint32_t b0, uint32_t b1) {
    asm volatile(
        "mma.sync.aligned.m16n8k16.row.col.f32.bf16.bf16.f32 "
        "{%0,%1,%2,%3}, {%4,%5,%6,%7}, {%8,%9}, {%0,%1,%2,%3};"
        : "+f"(d[0]), "+f"(d[1]), "+f"(d[2]), "+f"(d[3])
        : "r"(a[0]), "r"(a[1]), "r"(a[2]), "r"(a[3]), "r"(b0), "r"(b1));
}
__device__ __forceinline__ void cpasync16(uint32_t dst, const void* src) {
    asm volatile("cp.async.ca.shared.global [%0], [%1], 16;"
                 :: "r"(dst), "l"(src) : "memory");
}
__device__ __forceinline__ void cpasync16p(uint32_t dst, const void* src, uint32_t sz) {
    asm volatile("cp.async.ca.shared.global [%0], [%1], 16, %2;"
                 :: "r"(dst), "l"(src), "r"(sz) : "memory");
}
#define CP_COMMIT() asm volatile("cp.async.commit_group;" ::: "memory")
#define CP_WAIT2() asm volatile("cp.async.wait_group 2;" ::: "memory")
#define CP_WAIT0() asm volatile("cp.async.wait_group 0;" ::: "memory")

// truncation split of two f32 -> (hi-pair, lo-pair) packed bf16x2
__device__ __forceinline__ void split2(float h0, float h1, uint32_t& hiP, uint32_t& loP) {
    uint32_t b0 = __float_as_uint(h0), b1 = __float_as_uint(h1);
    hiP = __byte_perm(b0, b1, 0x7632);
    float r0 = h0 - __uint_as_float(b0 & 0xFFFF0000u);
    float r1 = h1 - __uint_as_float(b1 & 0xFFFF0000u);
    asm("cvt.rn.bf16x2.f32 %0, %1, %2;" : "=r"(loP) : "f"(r1), "f"(r0));
}

// ===================== device globals ======================================
// K'=64 split layouts: [hi(32), lo(32)] per 32-ic chunk. 128 B per row.
__device__ __align__(16) __nv_bfloat16 g_xsp[(size_t)NB * 8 * HH * WW * 64];
__device__ __align__(16) __nv_bfloat16 g_hs[(size_t)NB * 6 * OH * OW * 64];
__device__ __align__(16) __nv_bfloat16 g_wbs[6 * 9 * CO * 64];
__device__ __align__(16) __nv_bfloat16 g_wbs_up[9 * 8 * CM * 64];
__device__ float g_wsq_up[CM * CI];
__device__ float g_wsq_cv[CO * CM];
__device__ float g_s_up[NB * CI];
__device__ float g_s_cv[NB * CM];
__device__ float g_s_rgb[NB * CO];

// k'-offset tables (bf16 units): 3 cross terms via offsets.
__device__ __constant__ int AKo[6] = {0, 16, 32, 48, 0, 16};
__device__ __constant__ int BKo[6] = {0, 16, 0, 16, 32, 48};

// ---------------------------------------------------------------------------
__global__ void k_prep_w(const float* __restrict__ w_up,
                         const float* __restrict__ w_conv) {
    int idx = blockIdx.x * 256 + threadIdx.x;
    if (idx < CM * CI) {
        int o = idx / CI, i = idx % CI;
        const float* p = w_up + (i * CM + o) * 9;
        float acc = 0.f;
#pragma unroll
        for (int tt = 0; tt < 9; tt++) acc = fmaf(p[tt], p[tt], acc);
        g_wsq_up[idx] = acc;
    }
    if (idx < CO * CM) {
        int o = idx / CM, i = idx % CM;
        const float* p = w_conv + (o * CM + i) * 9;
        float acc = 0.f;
#pragma unroll
        for (int tt = 0; tt < 9; tt++) acc = fmaf(p[tt], p[tt], acc);
        g_wsq_cv[idx] = acc;
    }
    if (idx < 6 * 9 * CO * 64) {
        int k = idx % 64;
        int oc = (idx / 64) % CO;
        int t = (idx / (64 * CO)) % 9;
        int c = idx / (64 * CO * 9);
        int ic = c * 32 + (k & 31);
        float w = w_conv[(oc * CM + ic) * 9 + t];
        __nv_bfloat16 hi = __float2bfloat16(w);
        g_wbs[idx] = (k < 32) ? hi : __float2bfloat16(w - __bfloat162float(hi));
    }
    if (idx < 9 * 8 * CM * 64) {
        int k = idx % 64;
        int oc = (idx / 64) % CM;
        int c = (idx / (64 * CM)) % 8;
        int t = idx / (64 * CM * 8);
        int ic = c * 32 + (k & 31);
        float w = w_up[(ic * CM + oc) * 9 + t];
        __nv_bfloat16 hi = __float2bfloat16(w);
        g_wbs_up[idx] = (k < 32) ? hi : __float2bfloat16(w - __bfloat162float(hi));
    }
}

// ---------------------------------------------------------------------------
__global__ void k_style_all(const float* __restrict__ v,
                            const float* __restrict__ sw_up, const float* __restrict__ sb_up,
                            const float* __restrict__ sw_cv, const float* __restrict__ sb_cv,
                            const float* __restrict__ sw_rgb, const float* __restrict__ sb_rgb) {
    int warp = threadIdx.x >> 5, lane = threadIdx.x & 31;
    int cg = blockIdx.x * 8 + warp;
    int n = blockIdx.y;
    const float *sw, *sb;
    float* dst;
    int c;
    if (cg < 256)      { sw = sw_up;  sb = sb_up;  dst = g_s_up  + n * CI; c = cg; }
    else if (cg < 448) { sw = sw_cv;  sb = sb_cv;  dst = g_s_cv  + n * CM; c = cg - 256; }
    else               { sw = sw_rgb; sb = sb_rgb; dst = g_s_rgb + n * CO; c = cg - 448; }
    const float* vp = v + n * LV;
    const float* wp = sw + c * LV;
    float acc = 0.f;
#pragma unroll
    for (int l = lane; l < LV; l += 32) acc = fmaf(vp[l], wp[l], acc);
#pragma unroll
    for (int s = 16; s > 0; s >>= 1) acc += __shfl_xor_sync(0xFFFFFFFF, acc, s);
    if (lane == 0) dst[c] = acc + sb[c] + 1.0f;
}

// ---------------------------------------------------------------------------
__global__ void k_xsplit(const float* __restrict__ x) {
    __shared__ float sm[32][129];
    int py = blockIdx.x, c = blockIdx.y, n = blockIdx.z;
    int tid = threadIdx.x;
    for (int e = tid; e < 4096; e += 256) {
        int ic = e >> 7, px = e & 127;
        sm[ic][px] = x[(((size_t)n * CI + c * 32 + ic) << 14) + (py << 7) + px] *
                     g_s_up[n * CI + c * 32 + ic];
    }
    __syncthreads();
    int px = tid >> 1, hf = tid & 1;
    uint32_t hi[8], lo[8];
#pragma unroll
    for (int j = 0; j < 8; j++) {
        int p = hf * 8 + j;
        split2(sm[2 * p][px], sm[2 * p + 1][px], hi[j], lo[j]);
    }
    uint4* d4 = (uint4*)((uint32_t*)g_xsp +
                         ((size_t)(n * 8 + c) * 16384 + py * 128 + px) * 32);
    d4[hf * 2 + 0] = make_uint4(hi[0], hi[1], hi[2], hi[3]);
    d4[hf * 2 + 1] = make_uint4(hi[4], hi[5], hi[6], hi[7]);
    d4[4 + hf * 2 + 0] = make_uint4(lo[0], lo[1], lo[2], lo[3]);
    d4[4 + hf * 2 + 1] = make_uint4(lo[4], lo[5], lo[6], lo[7]);
}

// ---------------------------------------------------------------------------
// Upconv: parity-decomposed implicit GEMM, 512 thr, 4m x 4n (tile 32x48).
// R11 pipeline (monolithic per-chunk A prefetch) + in-kernel isg_up.
// ---------------------------------------------------------------------------
#define U_ABUF (153 * 144)
#define U_BBUF (192 * 144)
#define U_B0   (3 * U_ABUF)                    // 66096
#define U_ISG  (3 * U_ABUF + 3 * U_BBUF)       // 149040
#define U_SMEM (U_ISG + CM * 4)                // 149808
#define U_EPIP 200

__global__ __launch_bounds__(512, 1) void k_upconv_mma(
    const float* __restrict__ noise1, const float* __restrict__ b_up,
    const float* __restrict__ ns1p) {
    extern __shared__ __align__(16) char smem[];
    uint32_t sbase = smem_u32(smem);
    float* isg = (float*)(smem + U_ISG);

    int tid = threadIdx.x;
    int wid = tid >> 5, lane = tid & 31;
    int wm = wid & 3, wn = wid >> 2;
    int zc = blockIdx.z;
    int n = zc >> 2, cls = zc & 3;
    int y0 = blockIdx.y * 8, x0 = blockIdx.x * 16;

    int nt, ntsh, tapid[4], pixoff[4];
    if (cls == 0) {
        nt = 1; ntsh = 0;
        tapid[0] = 4; pixoff[0] = 0;
    } else if (cls == 1) {
        nt = 2; ntsh = 1;
        tapid[0] = 3; pixoff[0] = 1;
        tapid[1] = 5; pixoff[1] = 0;
    } else if (cls == 2) {
        nt = 2; ntsh = 1;
        tapid[0] = 1; pixoff[0] = 17;
        tapid[1] = 7; pixoff[1] = 0;
    } else {
        nt = 4; ntsh = 2;
        tapid[0] = 0; pixoff[0] = 18;
        tapid[1] = 2; pixoff[1] = 17;
        tapid[2] = 6; pixoff[2] = 1;
        tapid[3] = 8; pixoff[3] = 0;
    }
    const int NIT = nt * 8;

    int rowsel = lane & 15, ksel = lane >> 4;

    auto issueA = [&](int cc) {
        const char* asrc = (const char*)g_xsp + ((size_t)(n * 8 + cc) * 16384) * 128;
        uint32_t abuf = sbase + (cc % 3) * U_ABUF;
        for (int e = tid; e < 1224; e += 512) {
            int pix = e >> 3, q = e & 7;
            int ry = pix / 17, rx = pix % 17;
            int gy = y0 + ry, gx = x0 + rx;
            uint32_t ok = (gy < HH && gx < WW) ? 16u : 0u;
            int gyc = gy < HH - 1 ? gy : HH - 1;
            int gxc = gx < WW - 1 ? gx : WW - 1;
            cpasync16p(abuf + pix * 144 + q * 16,
                       asrc + ((size_t)gyc * 128 + gxc) * 128 + q * 16, ok);
        }
    };
    auto issueB = [&](int it2) {
        int c2 = it2 >> ntsh, ti2 = it2 & (nt - 1);
        const char* bsrc = (const char*)g_wbs_up + (size_t)(tapid[ti2] * 8 + c2) * 24576;
        uint32_t bbuf = sbase + U_B0 + (it2 % 3) * U_BBUF;
#pragma unroll
        for (int i = 0; i < 3; i++) {
            int e = tid + i * 512;
            int row = e >> 3, q = e & 7;
            cpasync16(bbuf + row * 144 + q * 16, bsrc + row * 128 + q * 16);
        }
    };

    float acc[2][6][4];
#pragma unroll
    for (int mi = 0; mi < 2; mi++)
#pragma unroll
        for (int ni = 0; ni < 6; ni++)
#pragma unroll
            for (int q = 0; q < 4; q++) acc[mi][ni][q] = 0.f;

    issueA(0); CP_COMMIT();
    issueB(0); CP_COMMIT();
    issueA(1); CP_COMMIT();
    issueB(1); CP_COMMIT();

    // isg_up in-kernel (overlaps prologue cp.async); 12 oc per warp.
    {
        const float* s = g_s_up + n * CI;
#pragma unroll
        for (int j = 0; j < 12; j++) {
            int o = wid * 12 + j;
            float a = 0.f;
            for (int i = lane; i < CI; i += 32) {
                float sv = s[i];
                a = fmaf(sv * sv, g_wsq_up[o * CI + i], a);
            }
#pragma unroll
            for (int sh = 16; sh > 0; sh >>= 1) a += __shfl_xor_sync(0xFFFFFFFF, a, sh);
            if (lane == 0) isg[o] = 1.0f / sqrtf(a + 1e-8f);
        }
    }

    for (int it = 0; it < NIT; it++) {
        int c = it >> ntsh, ti = it & (nt - 1);
        CP_WAIT2();
        __syncthreads();

        if (ti == 0 && c + 2 < 8) issueA(c + 2);
        CP_COMMIT();
        if (it + 2 < NIT) issueB(it + 2);
        CP_COMMIT();

        uint32_t sA = sbase + (c % 3) * U_ABUF;
        uint32_t sB = sbase + U_B0 + (it % 3) * U_BBUF;
        int ap0 = ((wm * 2 + 0) * 17 + rowsel + pixoff[ti]) * 144;
        int ap1 = ((wm * 2 + 1) * 17 + rowsel + pixoff[ti]) * 144;
#pragma unroll
        for (int kk = 0; kk < 6; kk++) {
            int akoff = (AKo[kk] + ksel * 8) * 2;
            int bkoff = (BKo[kk] + ksel * 8) * 2;
            uint32_t ar[2][4];
            ldsm_x4(ar[0], sA + ap0 + akoff);
            ldsm_x4(ar[1], sA + ap1 + akoff);
            uint32_t br[3][4];
#pragma unroll
            for (int nj = 0; nj < 3; nj++)
                ldsm_x4(br[nj], sB + (wn * 48 + nj * 16 + rowsel) * 144 + bkoff);
#pragma unroll
            for (int mi = 0; mi < 2; mi++)
#pragma unroll
                for (int ni = 0; ni < 6; ni++) {
                    int nj = ni >> 1, pr = ni & 1;
                    mma16816(acc[mi][ni], ar[mi], br[nj][pr], br[nj][pr + 2]);
                }
        }
        __syncthreads();
    }

    CP_WAIT0();
    __syncthreads();

    float* smf = (float*)smem;
#pragma unroll
    for (int mi = 0; mi < 2; mi++)
#pragma unroll
        for (int ni = 0; ni < 6; ni++) {
            int m = wm * 32 + mi * 16 + (lane >> 2);
            int col = wn * 48 + ni * 8 + (lane & 3) * 2;
            smf[m * U_EPIP + col] = acc[mi][ni][0];
            smf[m * U_EPIP + col + 1] = acc[mi][ni][1];
            smf[(m + 8) * U_EPIP + col] = acc[mi][ni][2];
            smf[(m + 8) * U_EPIP + col + 1] = acc[mi][ni][3];
        }
    __syncthreads();

    {
        int px = tid & 127;
        int ocl = tid >> 7;
        int my = px >> 4, mx = px & 15;
        int oy = 2 * (y0 + my) + (cls >> 1);
        int ox = 2 * (x0 + mx) + (cls & 1);
        float nz = (*ns1p) * noise1[(size_t)n * OH * OW + oy * OW + ox];
        const float* scv = g_s_cv + n * CM;
#pragma unroll 4
        for (int ob = 0; ob < 48; ob++) {
            int oc = ob * 4 + ocl;
            float d = smf[px * U_EPIP + oc];
            float val = fmaf(d, isg[oc], b_up[oc]) + nz;
            val = (val > 0.f ? val : 0.2f * val) * scv[oc];
            smf[px * U_EPIP + oc] = val;
        }
    }
    __syncthreads();

    {
        uint32_t* gbase = (uint32_t*)g_hs + (size_t)n * 6 * 65536 * 32;
        for (int e = tid; e < 6144; e += 512) {
            int q = e & 7;
            int pxc = e >> 3;
            int px = pxc & 127;
            int cc = pxc >> 7;
            int my = px >> 4, mx = px & 15;
            int pxg = (2 * (y0 + my) + (cls >> 1)) * OW + 2 * (x0 + mx) + (cls & 1);
            int r = q >> 2;
            int pp0 = (q & 3) << 2;
            const float* sp = smf + px * U_EPIP + cc * 32 + 2 * pp0;
            uint32_t w[4];
#pragma unroll
            for (int j = 0; j < 4; j++) {
                uint32_t hiP, loP;
                split2(sp[2 * j], sp[2 * j + 1], hiP, loP);
                w[j] = (r == 1) ? loP : hiP;
            }
            *(uint4*)(gbase + ((size_t)cc * 65536 + pxg) * 32 + q * 4) =
                make_uint4(w[0], w[1], w[2], w[3]);
        }
    }
}

// ---------------------------------------------------------------------------
// Conv2 + to-RGB fused: R11 config (M=128 px tile, 512 thr, 4m x 4n, 32x32)
// + in-kernel isg_cv.
// ---------------------------------------------------------------------------
#define C_ABUF (180 * 144)
#define C_BBUF (128 * 144)
#define C_B0   (3 * C_ABUF)                    // 77760
#define C_CF   (3 * C_ABUF + 3 * C_BBUF)       // 133056
#define C_ISG  (C_CF + 3 * CO * 4)             // 134592
#define C_SMEM (C_ISG + CO * 4)                // 135104
#define EPIP 133

__global__ __launch_bounds__(512, 1) void k_conv2_mma(
    const float* __restrict__ noise2, const float* __restrict__ b_conv,
    const float* __restrict__ ns2p, const float* __restrict__ y,
    const float* __restrict__ w_rgb, const float* __restrict__ b_rgb,
    float* __restrict__ out, float* __restrict__ yout) {
    extern __shared__ __align__(16) char smem[];
    uint32_t sbase = smem_u32(smem);
    float* cf = (float*)(smem + C_CF);
    float* isg = (float*)(smem + C_ISG);

    int tid = threadIdx.x;
    int wid = tid >> 5, lane = tid & 31;
    int wm = wid & 3, wn = wid >> 2;
    int n = blockIdx.z;
    int y0 = blockIdx.y * 8, x0 = blockIdx.x * 16;

    int rowsel = lane & 15, ksel = lane >> 4;

    auto issueA = [&](int cc) {
        const char* asrc = (const char*)g_hs + ((size_t)(n * 6 + cc) * 65536) * 128;
        uint32_t abuf = sbase + (cc % 3) * C_ABUF;
        for (int e = tid; e < 1440; e += 512) {
            int pix = e >> 3, q = e & 7;
            int ry = pix / 18, rx = pix % 18;
            int gy = y0 - 1 + ry, gx = x0 - 1 + rx;
            uint32_t ok = ((unsigned)gy < (unsigned)OH && (unsigned)gx < (unsigned)OW)
                              ? 16u : 0u;
            int gyc = gy < 0 ? 0 : (gy > OH - 1 ? OH - 1 : gy);
            int gxc = gx < 0 ? 0 : (gx > OW - 1 ? OW - 1 : gx);
            cpasync16p(abuf + pix * 144 + q * 16,
                       asrc + ((size_t)gyc * 256 + gxc) * 128 + q * 16, ok);
        }
    };
    auto issueB = [&](int it2) {
        const char* bsrc = (const char*)g_wbs + (size_t)it2 * 16384;
        uint32_t bbuf = sbase + C_B0 + (it2 % 3) * C_BBUF;
#pragma unroll
        for (int i = 0; i < 2; i++) {
            int e = tid + i * 512;
            int row = e >> 3, q = e & 7;
            cpasync16(bbuf + row * 144 + q * 16, bsrc + row * 128 + q * 16);
        }
    };

    float acc[2][4][4];
#pragma unroll
    for (int mi = 0; mi < 2; mi++)
#pragma unroll
        for (int ni = 0; ni < 4; ni++)
#pragma unroll
            for (int q = 0; q < 4; q++) acc[mi][ni][q] = 0.f;

    issueA(0); CP_COMMIT();
    issueB(0); CP_COMMIT();
    issueA(1); CP_COMMIT();
    issueB(1); CP_COMMIT();

    // cf + isg_cv in-kernel (overlaps prologue cp.async)
    if (tid < CO) {
        float s = g_s_rgb[n * CO + tid];
#pragma unroll
        for (int c = 0; c < 3; c++) cf[c * CO + tid] = w_rgb[c * CO + tid] * s;
    }
    {
        const float* s = g_s_cv + n * CM;
#pragma unroll
        for (int j = 0; j < 8; j++) {
            int o = wid * 8 + j;
            float a = 0.f;
            for (int i = lane; i < CM; i += 32) {
                float sv = s[i];
                a = fmaf(sv * sv, g_wsq_cv[o * CM + i], a);
            }
#pragma unroll
            for (int sh = 16; sh > 0; sh >>= 1) a += __shfl_xor_sync(0xFFFFFFFF, a, sh);
            if (lane == 0) isg[o] = 1.0f / sqrtf(a + 1e-8f);
        }
    }

    int c = 0, t = 0;
    for (int it = 0; it < 54; it++) {
        CP_WAIT2();
        __syncthreads();

        if (t == 0 && c + 2 < 6) issueA(c + 2);
        CP_COMMIT();
        if (it + 2 < 54) issueB(it + 2);
        CP_COMMIT();

        uint32_t sA = sbase + (c % 3) * C_ABUF;
        uint32_t sB = sbase + C_B0 + (it % 3) * C_BBUF;
        int ky = t / 3, kx = t % 3;
        int ap0 = ((ky + wm * 2 + 0) * 18 + kx + rowsel) * 144;
        int ap1 = ((ky + wm * 2 + 1) * 18 + kx + rowsel) * 144;
#pragma unroll
        for (int kk = 0; kk < 6; kk++) {
            int akoff = (AKo[kk] + ksel * 8) * 2;
            int bkoff = (BKo[kk] + ksel * 8) * 2;
            uint32_t ar[2][4];
            ldsm_x4(ar[0], sA + ap0 + akoff);
            ldsm_x4(ar[1], sA + ap1 + akoff);
            uint32_t br[2][4];
#pragma unroll
            for (int nj = 0; nj < 2; nj++)
                ldsm_x4(br[nj], sB + (wn * 32 + nj * 16 + rowsel) * 144 + bkoff);
#pragma unroll
            for (int mi = 0; mi < 2; mi++)
#pragma unroll
                for (int ni = 0; ni < 4; ni++) {
                    int nj = ni >> 1, pr = ni & 1;
                    mma16816(acc[mi][ni], ar[mi], br[nj][pr], br[nj][pr + 2]);
                }
        }
        __syncthreads();
        if (++t == 9) { t = 0; c++; }
    }

    CP_WAIT0();
    __syncthreads();

    float* smf = (float*)smem;
#pragma unroll
    for (int mi = 0; mi < 2; mi++)
#pragma unroll
        for (int ni = 0; ni < 4; ni++) {
            int m = wm * 32 + mi * 16 + (lane >> 2);
            int col = wn * 32 + ni * 8 + (lane & 3) * 2;
            smf[m * EPIP + col] = acc[mi][ni][0];
            smf[m * EPIP + col + 1] = acc[mi][ni][1];
            smf[(m + 8) * EPIP + col] = acc[mi][ni][2];
            smf[(m + 8) * EPIP + col + 1] = acc[mi][ni][3];
        }
    __syncthreads();

    {
        int px = tid & 127;
        int ocl = tid >> 7;
        int my = px >> 4, mx = px & 15;
        int yy = y0 + my, xx = x0 + mx;
        float nz = (*ns2p) * noise2[(n * OH + yy) * OW + xx];
#pragma unroll 4
        for (int ob = 0; ob < 32; ob++) {
            int oc = ob * 4 + ocl;
            float d = smf[px * EPIP + oc];
            float val = fmaf(d, isg[oc], b_conv[oc]) + nz;
            val = val > 0.f ? val : 0.2f * val;
            smf[px * EPIP + oc] = val;
            out[(((size_t)n * CO + oc) * OH + yy) * OW + xx] = val;
        }
    }
    __syncthreads();

    if (tid < 128) {
        int px = tid;
        int my = px >> 4, mx = px & 15;
        int oy = y0 + my, ox = x0 + mx;
        float a0 = b_rgb[0], a1 = b_rgb[1], a2 = b_rgb[2];
        const float* sp = smf + px * EPIP;
#pragma unroll 4
        for (int oc = 0; oc < CO; oc++) {
            float hv = sp[oc];
            a0 = fmaf(hv, cf[oc], a0);
            a1 = fmaf(hv, cf[CO + oc], a1);
            a2 = fmaf(hv, cf[2 * CO + oc], a2);
        }
        a0 = a0 > 0.f ? a0 : 0.2f * a0;
        a1 = a1 > 0.f ? a1 : 0.2f * a1;
        a2 = a2 > 0.f ? a2 : 0.2f * a2;
        float rr[3] = {a0, a1, a2};

        float fy = 0.5f * oy - 0.25f;
        int iyf = (int)floorf(fy);
        float wy = fy - (float)iyf;
        int iy0 = iyf < 0 ? 0 : iyf;
        int iy1 = (iyf + 1) > (HH - 1) ? (HH - 1) : (iyf + 1);
        float fx = 0.5f * ox - 0.25f;
        int ixf = (int)floorf(fx);
        float wx = fx - (float)ixf;
        int ix0 = ixf < 0 ? 0 : ixf;
        int ix1 = (ixf + 1) > (WW - 1) ? (WW - 1) : (ixf + 1);

#pragma unroll
        for (int ch = 0; ch < 3; ch++) {
            const float* yp = y + ((size_t)(n * 3 + ch) * HH) * WW;
            float v00 = yp[iy0 * WW + ix0], v01 = yp[iy0 * WW + ix1];
            float v10 = yp[iy1 * WW + ix0], v11 = yp[iy1 * WW + ix1];
            float vt = v00 + (v01 - v00) * wx;
            float vb = v10 + (v11 - v10) * wx;
            float val = vt + (vb - vt) * wy;
            yout[(((size_t)n * 3 + ch) * OH + oy) * OW + ox] = val + rr[ch];
        }
    }
}

// ---------------------------------------------------------------------------
extern "C" void kernel_launch(void* const* d_in, const int* in_sizes, int n_in,
                              void* d_out, int out_size) {
    const float* x       = (const float*)d_in[0];
    const float* v       = (const float*)d_in[1];
    const float* y       = (const float*)d_in[2];
    const float* noise1  = (const float*)d_in[3];
    const float* noise2  = (const float*)d_in[4];
    const float* w_up    = (const float*)d_in[5];
    const float* b_up    = (const float*)d_in[6];
    const float* sw_up   = (const float*)d_in[7];
    const float* sb_up   = (const float*)d_in[8];
    const float* w_conv  = (const float*)d_in[9];
    const float* b_conv  = (const float*)d_in[10];
    const float* sw_conv = (const float*)d_in[11];
    const float* sb_conv = (const float*)d_in[12];
    const float* w_rgb   = (const float*)d_in[13];
    const float* b_rgb   = (const float*)d_in[14];
    const float* sw_rgb  = (const float*)d_in[15];
    const float* sb_rgb  = (const float*)d_in[16];
    const float* ns1     = (const float*)d_in[17];
    const float* ns2     = (const float*)d_in[18];
    float* out = (float*)d_out;

    (void)in_sizes; (void)n_in; (void)out_size;

    k_prep_w<<<(9 * 8 * CM * 64 + 255) / 256, 256>>>(w_up, w_conv);

    dim3 gst(72, NB);
    k_style_all<<<gst, 256>>>(v, sw_up, sb_up, sw_conv, sb_conv, sw_rgb, sb_rgb);

    dim3 gxs(128, 8, NB);
    k_xsplit<<<gxs, 256>>>(x);

    cudaFuncSetAttribute(k_upconv_mma, cudaFuncAttributeMaxDynamicSharedMemorySize,
                         U_SMEM);
    dim3 gup(8, 16, NB * 4);
    k_upconv_mma<<<gup, 512, U_SMEM>>>(noise1, b_up, ns1);

    cudaFuncSetAttribute(k_conv2_mma, cudaFuncAttributeMaxDynamicSharedMemorySize,
                         C_SMEM);
    dim3 gcv(16, 32, NB);
    k_conv2_mma<<<gcv, 512, C_SMEM>>>(noise2, b_conv, ns2, y, w_rgb, b_rgb,
                                      out, out + (size_t)NB * CO * OH * OW);
}

// round 15
// speedup vs baseline: 1.6353x; 1.1260x over previous
#include <cuda_runtime.h>
#include <cuda_bf16.h>
#include <math.h>
#include <cstdint>

#define NB 8
#define CI 256
#define CM 192
#define CO 128
#define LV 512
#define HH 128
#define WW 128
#define OH 256
#define OW 256

// ===================== warp-MMA helpers (base ISA, sm_80+) =================
__device__ __forceinline__ uint32_t smem_u32(const void* p) {
    uint32_t a;
    asm("{ .reg .u64 t; cvta.to.shared.u64 t, %1; cvt.u32.u64 %0, t; }"
        : "=r"(a) : "l"(p));
    return a;
}
__device__ __forceinline__ void ldsm_x4(uint32_t* r, uint32_t addr) {
    asm volatile("ldmatrix.sync.aligned.m8n8.x4.shared.b16 {%0,%1,%2,%3}, [%4];"
                 : "=r"(r[0]), "=r"(r[1]), "=r"(r[2]), "=r"(r[3]) : "r"(addr));
}
__device__ __forceinline__ void mma16816(float* d, const uint32_t* a,
                                         uint32_t b0, uint32_t b1) {
    asm volatile(
        "mma.sync.aligned.m16n8k16.row.col.f32.bf16.bf16.f32 "
        "{%0,%1,%2,%3}, {%4,%5,%6,%7}, {%8,%9}, {%0,%1,%2,%3};"
        : "+f"(d[0]), "+f"(d[1]), "+f"(d[2]), "+f"(d[3])
        : "r"(a[0]), "r"(a[1]), "r"(a[2]), "r"(a[3]), "r"(b0), "r"(b1));
}
__device__ __forceinline__ void cpasync16(uint32_t dst, const void* src) {
    asm volatile("cp.async.ca.shared.global [%0], [%1], 16;"
                 :: "r"(dst), "l"(src) : "memory");
}
__device__ __forceinline__ void cpasync16p(uint32_t dst, const void* src, uint32_t sz) {
    asm volatile("cp.async.ca.shared.global [%0], [%1], 16, %2;"
                 :: "r"(dst), "l"(src), "r"(sz) : "memory");
}
#define CP_COMMIT() asm volatile("cp.async.commit_group;" ::: "memory")
#define CP_WAIT2() asm volatile("cp.async.wait_group 2;" ::: "memory")
#define CP_WAIT0() asm volatile("cp.async.wait_group 0;" ::: "memory")

// truncation split of two f32 -> (hi-pair, lo-pair) packed bf16x2
__device__ __forceinline__ void split2(float h0, float h1, uint32_t& hiP, uint32_t& loP) {
    uint32_t b0 = __float_as_uint(h0), b1 = __float_as_uint(h1);
    hiP = __byte_perm(b0, b1, 0x7632);
    float r0 = h0 - __uint_as_float(b0 & 0xFFFF0000u);
    float r1 = h1 - __uint_as_float(b1 & 0xFFFF0000u);
    asm("cvt.rn.bf16x2.f32 %0, %1, %2;" : "=r"(loP) : "f"(r1), "f"(r0));
}

// ===================== device globals ======================================
// K'=64 split layouts: [hi(32), lo(32)] per 32-ic chunk. 128 B per row.
__device__ __align__(16) __nv_bfloat16 g_xsp[(size_t)NB * 8 * HH * WW * 64];
__device__ __align__(16) __nv_bfloat16 g_hs[(size_t)NB * 6 * OH * OW * 64];
__device__ __align__(16) __nv_bfloat16 g_wbs[6 * 9 * CO * 64];
__device__ __align__(16) __nv_bfloat16 g_wbs_up[9 * 8 * CM * 64];
__device__ float g_wsq_up[CM * CI];
__device__ float g_wsq_cv[CO * CM];
__device__ float g_s_up[NB * CI];
__device__ float g_s_cv[NB * CM];
__device__ float g_s_rgb[NB * CO];
__device__ float g_isg_up[NB * CM];
__device__ float g_isg_cv[NB * CO];

// k'-offset tables (bf16 units): 3 cross terms via offsets.
__device__ __constant__ int AKo[6] = {0, 16, 32, 48, 0, 16};
__device__ __constant__ int BKo[6] = {0, 16, 0, 16, 32, 48};

// ---------------------------------------------------------------------------
__global__ void k_prep_w(const float* __restrict__ w_up,
                         const float* __restrict__ w_conv) {
    int idx = blockIdx.x * 256 + threadIdx.x;
    if (idx < CM * CI) {
        int o = idx / CI, i = idx % CI;
        const float* p = w_up + (i * CM + o) * 9;
        float acc = 0.f;
#pragma unroll
        for (int tt = 0; tt < 9; tt++) acc = fmaf(p[tt], p[tt], acc);
        g_wsq_up[idx] = acc;
    }
    if (idx < CO * CM) {
        int o = idx / CM, i = idx % CM;
        const float* p = w_conv + (o * CM + i) * 9;
        float acc = 0.f;
#pragma unroll
        for (int tt = 0; tt < 9; tt++) acc = fmaf(p[tt], p[tt], acc);
        g_wsq_cv[idx] = acc;
    }
    if (idx < 6 * 9 * CO * 64) {
        int k = idx % 64;
        int oc = (idx / 64) % CO;
        int t = (idx / (64 * CO)) % 9;
        int c = idx / (64 * CO * 9);
        int ic = c * 32 + (k & 31);
        float w = w_conv[(oc * CM + ic) * 9 + t];
        __nv_bfloat16 hi = __float2bfloat16(w);
        g_wbs[idx] = (k < 32) ? hi : __float2bfloat16(w - __bfloat162float(hi));
    }
    if (idx < 9 * 8 * CM * 64) {
        int k = idx % 64;
        int oc = (idx / 64) % CM;
        int c = (idx / (64 * CM)) % 8;
        int t = idx / (64 * CM * 8);
        int ic = c * 32 + (k & 31);
        float w = w_up[(ic * CM + oc) * 9 + t];
        __nv_bfloat16 hi = __float2bfloat16(w);
        g_wbs_up[idx] = (k < 32) ? hi : __float2bfloat16(w - __bfloat162float(hi));
    }
}

// ---------------------------------------------------------------------------
__global__ void k_style_all(const float* __restrict__ v,
                            const float* __restrict__ sw_up, const float* __restrict__ sb_up,
                            const float* __restrict__ sw_cv, const float* __restrict__ sb_cv,
                            const float* __restrict__ sw_rgb, const float* __restrict__ sb_rgb) {
    int warp = threadIdx.x >> 5, lane = threadIdx.x & 31;
    int cg = blockIdx.x * 8 + warp;
    int n = blockIdx.y;
    const float *sw, *sb;
    float* dst;
    int c;
    if (cg < 256)      { sw = sw_up;  sb = sb_up;  dst = g_s_up  + n * CI; c = cg; }
    else if (cg < 448) { sw = sw_cv;  sb = sb_cv;  dst = g_s_cv  + n * CM; c = cg - 256; }
    else               { sw = sw_rgb; sb = sb_rgb; dst = g_s_rgb + n * CO; c = cg - 448; }
    const float* vp = v + n * LV;
    const float* wp = sw + c * LV;
    float acc = 0.f;
#pragma unroll
    for (int l = lane; l < LV; l += 32) acc = fmaf(vp[l], wp[l], acc);
#pragma unroll
    for (int s = 16; s > 0; s >>= 1) acc += __shfl_xor_sync(0xFFFFFFFF, acc, s);
    if (lane == 0) dst[c] = acc + sb[c] + 1.0f;
}

// ---------------------------------------------------------------------------
__global__ void k_sigma_all() {
    int warp = threadIdx.x >> 5, lane = threadIdx.x & 31;
    int og = blockIdx.x * 4 + warp;
    int n = blockIdx.y;
    int IC, o;
    const float *wsq, *s;
    float* dst;
    if (og < CM) { IC = CI; o = og;       wsq = g_wsq_up; s = g_s_up + n * CI; dst = g_isg_up + n * CM; }
    else         { IC = CM; o = og - CM;  wsq = g_wsq_cv; s = g_s_cv + n * CM; dst = g_isg_cv + n * CO; }
    float acc = 0.f;
    for (int i = lane; i < IC; i += 32) {
        float sv = s[i];
        acc = fmaf(sv * sv, wsq[o * IC + i], acc);
    }
#pragma unroll
    for (int sh = 16; sh > 0; sh >>= 1) acc += __shfl_xor_sync(0xFFFFFFFF, acc, sh);
    if (lane == 0) dst[o] = 1.0f / sqrtf(acc + 1e-8f);
}

// ---------------------------------------------------------------------------
__global__ void k_xsplit(const float* __restrict__ x) {
    __shared__ float sm[32][129];
    int py = blockIdx.x, c = blockIdx.y, n = blockIdx.z;
    int tid = threadIdx.x;
    for (int e = tid; e < 4096; e += 256) {
        int ic = e >> 7, px = e & 127;
        sm[ic][px] = x[(((size_t)n * CI + c * 32 + ic) << 14) + (py << 7) + px] *
                     g_s_up[n * CI + c * 32 + ic];
    }
    __syncthreads();
    int px = tid >> 1, hf = tid & 1;
    uint32_t hi[8], lo[8];
#pragma unroll
    for (int j = 0; j < 8; j++) {
        int p = hf * 8 + j;
        split2(sm[2 * p][px], sm[2 * p + 1][px], hi[j], lo[j]);
    }
    uint4* d4 = (uint4*)((uint32_t*)g_xsp +
                         ((size_t)(n * 8 + c) * 16384 + py * 128 + px) * 32);
    d4[hf * 2 + 0] = make_uint4(hi[0], hi[1], hi[2], hi[3]);
    d4[hf * 2 + 1] = make_uint4(hi[4], hi[5], hi[6], hi[7]);
    d4[4 + hf * 2 + 0] = make_uint4(lo[0], lo[1], lo[2], lo[3]);
    d4[4 + hf * 2 + 1] = make_uint4(lo[4], lo[5], lo[6], lo[7]);
}

// ---------------------------------------------------------------------------
// Upconv: parity-decomposed implicit GEMM, 512 thr, 4m x 4n (tile 32x48).
// R11 pipeline; trailing per-iteration barrier elided (start barrier after
// CP_WAIT2 already orders buffer reuse).
// ---------------------------------------------------------------------------
#define U_ABUF (153 * 144)
#define U_BBUF (192 * 144)
#define U_B0   (3 * U_ABUF)                    // 66096
#define U_SMEM (3 * U_ABUF + 3 * U_BBUF)       // 149040
#define U_EPIP 200

__global__ __launch_bounds__(512, 1) void k_upconv_mma(
    const float* __restrict__ noise1, const float* __restrict__ b_up,
    const float* __restrict__ ns1p) {
    extern __shared__ __align__(16) char smem[];
    uint32_t sbase = smem_u32(smem);

    int tid = threadIdx.x;
    int wid = tid >> 5, lane = tid & 31;
    int wm = wid & 3, wn = wid >> 2;
    int zc = blockIdx.z;
    int n = zc >> 2, cls = zc & 3;
    int y0 = blockIdx.y * 8, x0 = blockIdx.x * 16;

    int nt, ntsh, tapid[4], pixoff[4];
    if (cls == 0) {
        nt = 1; ntsh = 0;
        tapid[0] = 4; pixoff[0] = 0;
    } else if (cls == 1) {
        nt = 2; ntsh = 1;
        tapid[0] = 3; pixoff[0] = 1;
        tapid[1] = 5; pixoff[1] = 0;
    } else if (cls == 2) {
        nt = 2; ntsh = 1;
        tapid[0] = 1; pixoff[0] = 17;
        tapid[1] = 7; pixoff[1] = 0;
    } else {
        nt = 4; ntsh = 2;
        tapid[0] = 0; pixoff[0] = 18;
        tapid[1] = 2; pixoff[1] = 17;
        tapid[2] = 6; pixoff[2] = 1;
        tapid[3] = 8; pixoff[3] = 0;
    }
    const int NIT = nt * 8;

    int rowsel = lane & 15, ksel = lane >> 4;

    auto issueA = [&](int cc) {
        const char* asrc = (const char*)g_xsp + ((size_t)(n * 8 + cc) * 16384) * 128;
        uint32_t abuf = sbase + (cc % 3) * U_ABUF;
        for (int e = tid; e < 1224; e += 512) {
            int pix = e >> 3, q = e & 7;
            int ry = pix / 17, rx = pix % 17;
            int gy = y0 + ry, gx = x0 + rx;
            uint32_t ok = (gy < HH && gx < WW) ? 16u : 0u;
            int gyc = gy < HH - 1 ? gy : HH - 1;
            int gxc = gx < WW - 1 ? gx : WW - 1;
            cpasync16p(abuf + pix * 144 + q * 16,
                       asrc + ((size_t)gyc * 128 + gxc) * 128 + q * 16, ok);
        }
    };
    auto issueB = [&](int it2) {
        int c2 = it2 >> ntsh, ti2 = it2 & (nt - 1);
        const char* bsrc = (const char*)g_wbs_up + (size_t)(tapid[ti2] * 8 + c2) * 24576;
        uint32_t bbuf = sbase + U_B0 + (it2 % 3) * U_BBUF;
#pragma unroll
        for (int i = 0; i < 3; i++) {
            int e = tid + i * 512;
            int row = e >> 3, q = e & 7;
            cpasync16(bbuf + row * 144 + q * 16, bsrc + row * 128 + q * 16);
        }
    };

    float acc[2][6][4];
#pragma unroll
    for (int mi = 0; mi < 2; mi++)
#pragma unroll
        for (int ni = 0; ni < 6; ni++)
#pragma unroll
            for (int q = 0; q < 4; q++) acc[mi][ni][q] = 0.f;

    issueA(0); CP_COMMIT();
    issueB(0); CP_COMMIT();
    issueA(1); CP_COMMIT();
    issueB(1); CP_COMMIT();

    for (int it = 0; it < NIT; it++) {
        int c = it >> ntsh, ti = it & (nt - 1);
        CP_WAIT2();
        __syncthreads();

        if (ti == 0 && c + 2 < 8) issueA(c + 2);
        CP_COMMIT();
        if (it + 2 < NIT) issueB(it + 2);
        CP_COMMIT();

        uint32_t sA = sbase + (c % 3) * U_ABUF;
        uint32_t sB = sbase + U_B0 + (it % 3) * U_BBUF;
        int ap0 = ((wm * 2 + 0) * 17 + rowsel + pixoff[ti]) * 144;
        int ap1 = ((wm * 2 + 1) * 17 + rowsel + pixoff[ti]) * 144;
#pragma unroll
        for (int kk = 0; kk < 6; kk++) {
            int akoff = (AKo[kk] + ksel * 8) * 2;
            int bkoff = (BKo[kk] + ksel * 8) * 2;
            uint32_t ar[2][4];
            ldsm_x4(ar[0], sA + ap0 + akoff);
            ldsm_x4(ar[1], sA + ap1 + akoff);
            uint32_t br[3][4];
#pragma unroll
            for (int nj = 0; nj < 3; nj++)
                ldsm_x4(br[nj], sB + (wn * 48 + nj * 16 + rowsel) * 144 + bkoff);
#pragma unroll
            for (int mi = 0; mi < 2; mi++)
#pragma unroll
                for (int ni = 0; ni < 6; ni++) {
                    int nj = ni >> 1, pr = ni & 1;
                    mma16816(acc[mi][ni], ar[mi], br[nj][pr], br[nj][pr + 2]);
                }
        }
        // trailing barrier elided: start barrier of it+1 orders buffer reuse
    }

    CP_WAIT0();
    __syncthreads();

    float* smf = (float*)smem;
#pragma unroll
    for (int mi = 0; mi < 2; mi++)
#pragma unroll
        for (int ni = 0; ni < 6; ni++) {
            int m = wm * 32 + mi * 16 + (lane >> 2);
            int col = wn * 48 + ni * 8 + (lane & 3) * 2;
            smf[m * U_EPIP + col] = acc[mi][ni][0];
            smf[m * U_EPIP + col + 1] = acc[mi][ni][1];
            smf[(m + 8) * U_EPIP + col] = acc[mi][ni][2];
            smf[(m + 8) * U_EPIP + col + 1] = acc[mi][ni][3];
        }
    __syncthreads();

    {
        int px = tid & 127;
        int ocl = tid >> 7;
        int my = px >> 4, mx = px & 15;
        int oy = 2 * (y0 + my) + (cls >> 1);
        int ox = 2 * (x0 + mx) + (cls & 1);
        float nz = (*ns1p) * noise1[(size_t)n * OH * OW + oy * OW + ox];
        const float* isgp = g_isg_up + n * CM;
        const float* scv = g_s_cv + n * CM;
#pragma unroll 4
        for (int ob = 0; ob < 48; ob++) {
            int oc = ob * 4 + ocl;
            float d = smf[px * U_EPIP + oc];
            float val = fmaf(d, isgp[oc], b_up[oc]) + nz;
            val = (val > 0.f ? val : 0.2f * val) * scv[oc];
            smf[px * U_EPIP + oc] = val;
        }
    }
    __syncthreads();

    {
        uint32_t* gbase = (uint32_t*)g_hs + (size_t)n * 6 * 65536 * 32;
        for (int e = tid; e < 6144; e += 512) {
            int q = e & 7;
            int pxc = e >> 3;
            int px = pxc & 127;
            int cc = pxc >> 7;
            int my = px >> 4, mx = px & 15;
            int pxg = (2 * (y0 + my) + (cls >> 1)) * OW + 2 * (x0 + mx) + (cls & 1);
            int r = q >> 2;
            int pp0 = (q & 3) << 2;
            const float* sp = smf + px * U_EPIP + cc * 32 + 2 * pp0;
            uint32_t w[4];
#pragma unroll
            for (int j = 0; j < 4; j++) {
                uint32_t hiP, loP;
                split2(sp[2 * j], sp[2 * j + 1], hiP, loP);
                w[j] = (r == 1) ? loP : hiP;
            }
            *(uint4*)(gbase + ((size_t)cc * 65536 + pxg) * 32 + q * 4) =
                make_uint4(w[0], w[1], w[2], w[3]);
        }
    }
}

// ---------------------------------------------------------------------------
// Conv2 + to-RGB fused: R11 config (M=128 px tile, 512 thr, 4m x 4n, 32x32);
// trailing per-iteration barrier elided.
// ---------------------------------------------------------------------------
#define C_ABUF (180 * 144)
#define C_BBUF (128 * 144)
#define C_B0   (3 * C_ABUF)                    // 77760
#define C_CF   (3 * C_ABUF + 3 * C_BBUF)       // 133056
#define C_SMEM (C_CF + 3 * CO * 4)             // 134592
#define EPIP 133

__global__ __launch_bounds__(512, 1) void k_conv2_mma(
    const float* __restrict__ noise2, const float* __restrict__ b_conv,
    const float* __restrict__ ns2p, const float* __restrict__ y,
    const float* __restrict__ w_rgb, const float* __restrict__ b_rgb,
    float* __restrict__ out, float* __restrict__ yout) {
    extern __shared__ __align__(16) char smem[];
    uint32_t sbase = smem_u32(smem);
    float* cf = (float*)(smem + C_CF);

    int tid = threadIdx.x;
    int wid = tid >> 5, lane = tid & 31;
    int wm = wid & 3, wn = wid >> 2;
    int n = blockIdx.z;
    int y0 = blockIdx.y * 8, x0 = blockIdx.x * 16;

    if (tid < CO) {
        float s = g_s_rgb[n * CO + tid];
#pragma unroll
        for (int c = 0; c < 3; c++) cf[c * CO + tid] = w_rgb[c * CO + tid] * s;
    }

    int rowsel = lane & 15, ksel = lane >> 4;

    auto issueA = [&](int cc) {
        const char* asrc = (const char*)g_hs + ((size_t)(n * 6 + cc) * 65536) * 128;
        uint32_t abuf = sbase + (cc % 3) * C_ABUF;
        for (int e = tid; e < 1440; e += 512) {
            int pix = e >> 3, q = e & 7;
            int ry = pix / 18, rx = pix % 18;
            int gy = y0 - 1 + ry, gx = x0 - 1 + rx;
            uint32_t ok = ((unsigned)gy < (unsigned)OH && (unsigned)gx < (unsigned)OW)
                              ? 16u : 0u;
            int gyc = gy < 0 ? 0 : (gy > OH - 1 ? OH - 1 : gy);
            int gxc = gx < 0 ? 0 : (gx > OW - 1 ? OW - 1 : gx);
            cpasync16p(abuf + pix * 144 + q * 16,
                       asrc + ((size_t)gyc * 256 + gxc) * 128 + q * 16, ok);
        }
    };
    auto issueB = [&](int it2) {
        const char* bsrc = (const char*)g_wbs + (size_t)it2 * 16384;
        uint32_t bbuf = sbase + C_B0 + (it2 % 3) * C_BBUF;
#pragma unroll
        for (int i = 0; i < 2; i++) {
            int e = tid + i * 512;
            int row = e >> 3, q = e & 7;
            cpasync16(bbuf + row * 144 + q * 16, bsrc + row * 128 + q * 16);
        }
    };

    float acc[2][4][4];
#pragma unroll
    for (int mi = 0; mi < 2; mi++)
#pragma unroll
        for (int ni = 0; ni < 4; ni++)
#pragma unroll
            for (int q = 0; q < 4; q++) acc[mi][ni][q] = 0.f;

    issueA(0); CP_COMMIT();
    issueB(0); CP_COMMIT();
    issueA(1); CP_COMMIT();
    issueB(1); CP_COMMIT();

    int c = 0, t = 0;
    for (int it = 0; it < 54; it++) {
        CP_WAIT2();
        __syncthreads();

        if (t == 0 && c + 2 < 6) issueA(c + 2);
        CP_COMMIT();
        if (it + 2 < 54) issueB(it + 2);
        CP_COMMIT();

        uint32_t sA = sbase + (c % 3) * C_ABUF;
        uint32_t sB = sbase + C_B0 + (it % 3) * C_BBUF;
        int ky = t / 3, kx = t % 3;
        int ap0 = ((ky + wm * 2 + 0) * 18 + kx + rowsel) * 144;
        int ap1 = ((ky + wm * 2 + 1) * 18 + kx + rowsel) * 144;
#pragma unroll
        for (int kk = 0; kk < 6; kk++) {
            int akoff = (AKo[kk] + ksel * 8) * 2;
            int bkoff = (BKo[kk] + ksel * 8) * 2;
            uint32_t ar[2][4];
            ldsm_x4(ar[0], sA + ap0 + akoff);
            ldsm_x4(ar[1], sA + ap1 + akoff);
            uint32_t br[2][4];
#pragma unroll
            for (int nj = 0; nj < 2; nj++)
                ldsm_x4(br[nj], sB + (wn * 32 + nj * 16 + rowsel) * 144 + bkoff);
#pragma unroll
            for (int mi = 0; mi < 2; mi++)
#pragma unroll
                for (int ni = 0; ni < 4; ni++) {
                    int nj = ni >> 1, pr = ni & 1;
                    mma16816(acc[mi][ni], ar[mi], br[nj][pr], br[nj][pr + 2]);
                }
        }
        // trailing barrier elided: start barrier of it+1 orders buffer reuse
        if (++t == 9) { t = 0; c++; }
    }

    CP_WAIT0();
    __syncthreads();

    float* smf = (float*)smem;
#pragma unroll
    for (int mi = 0; mi < 2; mi++)
#pragma unroll
        for (int ni = 0; ni < 4; ni++) {
            int m = wm * 32 + mi * 16 + (lane >> 2);
            int col = wn * 32 + ni * 8 + (lane & 3) * 2;
            smf[m * EPIP + col] = acc[mi][ni][0];
            smf[m * EPIP + col + 1] = acc[mi][ni][1];
            smf[(m + 8) * EPIP + col] = acc[mi][ni][2];
            smf[(m + 8) * EPIP + col + 1] = acc[mi][ni][3];
        }
    __syncthreads();

    {
        int px = tid & 127;
        int ocl = tid >> 7;
        int my = px >> 4, mx = px & 15;
        int yy = y0 + my, xx = x0 + mx;
        float nz = (*ns2p) * noise2[(n * OH + yy) * OW + xx];
        const float* isgp = g_isg_cv + n * CO;
#pragma unroll 4
        for (int ob = 0; ob < 32; ob++) {
            int oc = ob * 4 + ocl;
            float d = smf[px * EPIP + oc];
            float val = fmaf(d, isgp[oc], b_conv[oc]) + nz;
            val = val > 0.f ? val : 0.2f * val;
            smf[px * EPIP + oc] = val;
            out[(((size_t)n * CO + oc) * OH + yy) * OW + xx] = val;
        }
    }
    __syncthreads();

    if (tid < 128) {
        int px = tid;
        int my = px >> 4, mx = px & 15;
        int oy = y0 + my, ox = x0 + mx;
        float a0 = b_rgb[0], a1 = b_rgb[1], a2 = b_rgb[2];
        const float* sp = smf + px * EPIP;
#pragma unroll 4
        for (int oc = 0; oc < CO; oc++) {
            float hv = sp[oc];
            a0 = fmaf(hv, cf[oc], a0);
            a1 = fmaf(hv, cf[CO + oc], a1);
            a2 = fmaf(hv, cf[2 * CO + oc], a2);
        }
        a0 = a0 > 0.f ? a0 : 0.2f * a0;
        a1 = a1 > 0.f ? a1 : 0.2f * a1;
        a2 = a2 > 0.f ? a2 : 0.2f * a2;
        float rr[3] = {a0, a1, a2};

        float fy = 0.5f * oy - 0.25f;
        int iyf = (int)floorf(fy);
        float wy = fy - (float)iyf;
        int iy0 = iyf < 0 ? 0 : iyf;
        int iy1 = (iyf + 1) > (HH - 1) ? (HH - 1) : (iyf + 1);
        float fx = 0.5f * ox - 0.25f;
        int ixf = (int)floorf(fx);
        float wx = fx - (float)ixf;
        int ix0 = ixf < 0 ? 0 : ixf;
        int ix1 = (ixf + 1) > (WW - 1) ? (WW - 1) : (ixf + 1);

#pragma unroll
        for (int ch = 0; ch < 3; ch++) {
            const float* yp = y + ((size_t)(n * 3 + ch) * HH) * WW;
            float v00 = yp[iy0 * WW + ix0], v01 = yp[iy0 * WW + ix1];
            float v10 = yp[iy1 * WW + ix0], v11 = yp[iy1 * WW + ix1];
            float vt = v00 + (v01 - v00) * wx;
            float vb = v10 + (v11 - v10) * wx;
            float val = vt + (vb - vt) * wy;
            yout[(((size_t)n * 3 + ch) * OH + oy) * OW + ox] = val + rr[ch];
        }
    }
}

// ---------------------------------------------------------------------------
extern "C" void kernel_launch(void* const* d_in, const int* in_sizes, int n_in,
                              void* d_out, int out_size) {
    const float* x       = (const float*)d_in[0];
    const float* v       = (const float*)d_in[1];
    const float* y       = (const float*)d_in[2];
    const float* noise1  = (const float*)d_in[3];
    const float* noise2  = (const float*)d_in[4];
    const float* w_up    = (const float*)d_in[5];
    const float* b_up    = (const float*)d_in[6];
    const float* sw_up   = (const float*)d_in[7];
    const float* sb_up   = (const float*)d_in[8];
    const float* w_conv  = (const float*)d_in[9];
    const float* b_conv  = (const float*)d_in[10];
    const float* sw_conv = (const float*)d_in[11];
    const float* sb_conv = (const float*)d_in[12];
    const float* w_rgb   = (const float*)d_in[13];
    const float* b_rgb   = (const float*)d_in[14];
    const float* sw_rgb  = (const float*)d_in[15];
    const float* sb_rgb  = (const float*)d_in[16];
    const float* ns1     = (const float*)d_in[17];
    const float* ns2     = (const float*)d_in[18];
    float* out = (float*)d_out;

    (void)in_sizes; (void)n_in; (void)out_size;

    k_prep_w<<<(9 * 8 * CM * 64 + 255) / 256, 256>>>(w_up, w_conv);

    dim3 gst(72, NB);
    k_style_all<<<gst, 256>>>(v, sw_up, sb_up, sw_conv, sb_conv, sw_rgb, sb_rgb);

    dim3 gsg(80, NB);
    k_sigma_all<<<gsg, 128>>>();

    dim3 gxs(128, 8, NB);
    k_xsplit<<<gxs, 256>>>(x);

    cudaFuncSetAttribute(k_upconv_mma, cudaFuncAttributeMaxDynamicSharedMemorySize,
                         U_SMEM);
    dim3 gup(8, 16, NB * 4);
    k_upconv_mma<<<gup, 512, U_SMEM>>>(noise1, b_up, ns1);

    cudaFuncSetAttribute(k_conv2_mma, cudaFuncAttributeMaxDynamicSharedMemorySize,
                         C_SMEM);
    dim3 gcv(16, 32, NB);
    k_conv2_mma<<<gcv, 512, C_SMEM>>>(noise2, b_conv, ns2, y, w_rgb, b_rgb,
                                      out, out + (size_t)NB * CO * OH * OW);
}

// round 17
// speedup vs baseline: 1.6663x; 1.0190x over previous
#include <cuda_runtime.h>
#include <cuda_bf16.h>
#include <math.h>
#include <cstdint>

#define NB 8
#define CI 256
#define CM 192
#define CO 128
#define LV 512
#define HH 128
#define WW 128
#define OH 256
#define OW 256

// ===================== warp-MMA helpers (base ISA, sm_80+) =================
__device__ __forceinline__ uint32_t smem_u32(const void* p) {
    uint32_t a;
    asm("{ .reg .u64 t; cvta.to.shared.u64 t, %1; cvt.u32.u64 %0, t; }"
        : "=r"(a) : "l"(p));
    return a;
}
__device__ __forceinline__ void ldsm_x4(uint32_t* r, uint32_t addr) {
    asm volatile("ldmatrix.sync.aligned.m8n8.x4.shared.b16 {%0,%1,%2,%3}, [%4];"
                 : "=r"(r[0]), "=r"(r[1]), "=r"(r[2]), "=r"(r[3]) : "r"(addr));
}
__device__ __forceinline__ void mma16816(float* d, const uint32_t* a,
                                         uint32_t b0, uint32_t b1) {
    asm volatile(
        "mma.sync.aligned.m16n8k16.row.col.f32.bf16.bf16.f32 "
        "{%0,%1,%2,%3}, {%4,%5,%6,%7}, {%8,%9}, {%0,%1,%2,%3};"
        : "+f"(d[0]), "+f"(d[1]), "+f"(d[2]), "+f"(d[3])
        : "r"(a[0]), "r"(a[1]), "r"(a[2]), "r"(a[3]), "r"(b0), "r"(b1));
}
__device__ __forceinline__ void cpasync16(uint32_t dst, const void* src) {
    asm volatile("cp.async.ca.shared.global [%0], [%1], 16;"
                 :: "r"(dst), "l"(src) : "memory");
}
__device__ __forceinline__ void cpasync16p(uint32_t dst, const void* src, uint32_t sz) {
    asm volatile("cp.async.ca.shared.global [%0], [%1], 16, %2;"
                 :: "r"(dst), "l"(src), "r"(sz) : "memory");
}
#define CP_COMMIT() asm volatile("cp.async.commit_group;" ::: "memory")
#define CP_WAIT2() asm volatile("cp.async.wait_group 2;" ::: "memory")
#define CP_WAIT0() asm volatile("cp.async.wait_group 0;" ::: "memory")

// truncation split of two f32 -> (hi-pair, lo-pair) packed bf16x2
__device__ __forceinline__ void split2(float h0, float h1, uint32_t& hiP, uint32_t& loP) {
    uint32_t b0 = __float_as_uint(h0), b1 = __float_as_uint(h1);
    hiP = __byte_perm(b0, b1, 0x7632);
    float r0 = h0 - __uint_as_float(b0 & 0xFFFF0000u);
    float r1 = h1 - __uint_as_float(b1 & 0xFFFF0000u);
    asm("cvt.rn.bf16x2.f32 %0, %1, %2;" : "=r"(loP) : "f"(r1), "f"(r0));
}

// ===================== device globals ======================================
// K'=64 split layouts: [hi(32), lo(32)] per 32-ic chunk. 128 B per row.
__device__ __align__(16) __nv_bfloat16 g_xsp[(size_t)NB * 8 * HH * WW * 64];
__device__ __align__(16) __nv_bfloat16 g_hs[(size_t)NB * 6 * OH * OW * 64];
__device__ __align__(16) __nv_bfloat16 g_wbs[6 * 9 * CO * 64];
__device__ __align__(16) __nv_bfloat16 g_wbs_up[9 * 8 * CM * 64];
__device__ float g_wsq_up[CM * CI];
__device__ float g_wsq_cv[CO * CM];
__device__ float g_s_up[NB * CI];
__device__ float g_s_cv[NB * CM];
__device__ float g_s_rgb[NB * CO];
__device__ float g_isg_up[NB * CM];
__device__ float g_isg_cv[NB * CO];

// k'-offset tables (bf16 units): 3 cross terms via offsets.
__device__ __constant__ int AKo[6] = {0, 16, 32, 48, 0, 16};
__device__ __constant__ int BKo[6] = {0, 16, 0, 16, 32, 48};

// ---------------------------------------------------------------------------
__global__ void k_prep_w(const float* __restrict__ w_up,
                         const float* __restrict__ w_conv) {
    int idx = blockIdx.x * 256 + threadIdx.x;
    if (idx < CM * CI) {
        int o = idx / CI, i = idx % CI;
        const float* p = w_up + (i * CM + o) * 9;
        float acc = 0.f;
#pragma unroll
        for (int tt = 0; tt < 9; tt++) acc = fmaf(p[tt], p[tt], acc);
        g_wsq_up[idx] = acc;
    }
    if (idx < CO * CM) {
        int o = idx / CM, i = idx % CM;
        const float* p = w_conv + (o * CM + i) * 9;
        float acc = 0.f;
#pragma unroll
        for (int tt = 0; tt < 9; tt++) acc = fmaf(p[tt], p[tt], acc);
        g_wsq_cv[idx] = acc;
    }
    if (idx < 6 * 9 * CO * 64) {
        int k = idx % 64;
        int oc = (idx / 64) % CO;
        int t = (idx / (64 * CO)) % 9;
        int c = idx / (64 * CO * 9);
        int ic = c * 32 + (k & 31);
        float w = w_conv[(oc * CM + ic) * 9 + t];
        __nv_bfloat16 hi = __float2bfloat16(w);
        g_wbs[idx] = (k < 32) ? hi : __float2bfloat16(w - __bfloat162float(hi));
    }
    if (idx < 9 * 8 * CM * 64) {
        int k = idx % 64;
        int oc = (idx / 64) % CM;
        int c = (idx / (64 * CM)) % 8;
        int t = idx / (64 * CM * 8);
        int ic = c * 32 + (k & 31);
        float w = w_up[(ic * CM + oc) * 9 + t];
        __nv_bfloat16 hi = __float2bfloat16(w);
        g_wbs_up[idx] = (k < 32) ? hi : __float2bfloat16(w - __bfloat162float(hi));
    }
}

// ---------------------------------------------------------------------------
__global__ void k_style_all(const float* __restrict__ v,
                            const float* __restrict__ sw_up, const float* __restrict__ sb_up,
                            const float* __restrict__ sw_cv, const float* __restrict__ sb_cv,
                            const float* __restrict__ sw_rgb, const float* __restrict__ sb_rgb) {
    int warp = threadIdx.x >> 5, lane = threadIdx.x & 31;
    int cg = blockIdx.x * 8 + warp;
    int n = blockIdx.y;
    const float *sw, *sb;
    float* dst;
    int c;
    if (cg < 256)      { sw = sw_up;  sb = sb_up;  dst = g_s_up  + n * CI; c = cg; }
    else if (cg < 448) { sw = sw_cv;  sb = sb_cv;  dst = g_s_cv  + n * CM; c = cg - 256; }
    else               { sw = sw_rgb; sb = sb_rgb; dst = g_s_rgb + n * CO; c = cg - 448; }
    const float* vp = v + n * LV;
    const float* wp = sw + c * LV;
    float acc = 0.f;
#pragma unroll
    for (int l = lane; l < LV; l += 32) acc = fmaf(vp[l], wp[l], acc);
#pragma unroll
    for (int s = 16; s > 0; s >>= 1) acc += __shfl_xor_sync(0xFFFFFFFF, acc, s);
    if (lane == 0) dst[c] = acc + sb[c] + 1.0f;
}

// ---------------------------------------------------------------------------
__global__ void k_sigma_all() {
    int warp = threadIdx.x >> 5, lane = threadIdx.x & 31;
    int og = blockIdx.x * 4 + warp;
    int n = blockIdx.y;
    int IC, o;
    const float *wsq, *s;
    float* dst;
    if (og < CM) { IC = CI; o = og;       wsq = g_wsq_up; s = g_s_up + n * CI; dst = g_isg_up + n * CM; }
    else         { IC = CM; o = og - CM;  wsq = g_wsq_cv; s = g_s_cv + n * CM; dst = g_isg_cv + n * CO; }
    float acc = 0.f;
    for (int i = lane; i < IC; i += 32) {
        float sv = s[i];
        acc = fmaf(sv * sv, wsq[o * IC + i], acc);
    }
#pragma unroll
    for (int sh = 16; sh > 0; sh >>= 1) acc += __shfl_xor_sync(0xFFFFFFFF, acc, sh);
    if (lane == 0) dst[o] = 1.0f / sqrtf(acc + 1e-8f);
}

// ---------------------------------------------------------------------------
__global__ void k_xsplit(const float* __restrict__ x) {
    __shared__ float sm[32][129];
    int py = blockIdx.x, c = blockIdx.y, n = blockIdx.z;
    int tid = threadIdx.x;
    for (int e = tid; e < 4096; e += 256) {
        int ic = e >> 7, px = e & 127;
        sm[ic][px] = x[(((size_t)n * CI + c * 32 + ic) << 14) + (py << 7) + px] *
                     g_s_up[n * CI + c * 32 + ic];
    }
    __syncthreads();
    int px = tid >> 1, hf = tid & 1;
    uint32_t hi[8], lo[8];
#pragma unroll
    for (int j = 0; j < 8; j++) {
        int p = hf * 8 + j;
        split2(sm[2 * p][px], sm[2 * p + 1][px], hi[j], lo[j]);
    }
    uint4* d4 = (uint4*)((uint32_t*)g_xsp +
                         ((size_t)(n * 8 + c) * 16384 + py * 128 + px) * 32);
    d4[hf * 2 + 0] = make_uint4(hi[0], hi[1], hi[2], hi[3]);
    d4[hf * 2 + 1] = make_uint4(hi[4], hi[5], hi[6], hi[7]);
    d4[4 + hf * 2 + 0] = make_uint4(lo[0], lo[1], lo[2], lo[3]);
    d4[4 + hf * 2 + 1] = make_uint4(lo[4], lo[5], lo[6], lo[7]);
}

// ---------------------------------------------------------------------------
// Upconv: parity-decomposed implicit GEMM, 512 thr, 4m x 4n (tile 32x48).
// R15 config (verified 3417 us), unchanged.
// ---------------------------------------------------------------------------
#define U_ABUF (153 * 144)
#define U_BBUF (192 * 144)
#define U_B0   (3 * U_ABUF)                    // 66096
#define U_SMEM (3 * U_ABUF + 3 * U_BBUF)       // 149040
#define U_EPIP 200

__global__ __launch_bounds__(512, 1) void k_upconv_mma(
    const float* __restrict__ noise1, const float* __restrict__ b_up,
    const float* __restrict__ ns1p) {
    extern __shared__ __align__(16) char smem[];
    uint32_t sbase = smem_u32(smem);

    int tid = threadIdx.x;
    int wid = tid >> 5, lane = tid & 31;
    int wm = wid & 3, wn = wid >> 2;
    int zc = blockIdx.z;
    int n = zc >> 2, cls = zc & 3;
    int y0 = blockIdx.y * 8, x0 = blockIdx.x * 16;

    int nt, ntsh, tapid[4], pixoff[4];
    if (cls == 0) {
        nt = 1; ntsh = 0;
        tapid[0] = 4; pixoff[0] = 0;
    } else if (cls == 1) {
        nt = 2; ntsh = 1;
        tapid[0] = 3; pixoff[0] = 1;
        tapid[1] = 5; pixoff[1] = 0;
    } else if (cls == 2) {
        nt = 2; ntsh = 1;
        tapid[0] = 1; pixoff[0] = 17;
        tapid[1] = 7; pixoff[1] = 0;
    } else {
        nt = 4; ntsh = 2;
        tapid[0] = 0; pixoff[0] = 18;
        tapid[1] = 2; pixoff[1] = 17;
        tapid[2] = 6; pixoff[2] = 1;
        tapid[3] = 8; pixoff[3] = 0;
    }
    const int NIT = nt * 8;

    int rowsel = lane & 15, ksel = lane >> 4;

    auto issueA = [&](int cc) {
        const char* asrc = (const char*)g_xsp + ((size_t)(n * 8 + cc) * 16384) * 128;
        uint32_t abuf = sbase + (cc % 3) * U_ABUF;
        for (int e = tid; e < 1224; e += 512) {
            int pix = e >> 3, q = e & 7;
            int ry = pix / 17, rx = pix % 17;
            int gy = y0 + ry, gx = x0 + rx;
            uint32_t ok = (gy < HH && gx < WW) ? 16u : 0u;
            int gyc = gy < HH - 1 ? gy : HH - 1;
            int gxc = gx < WW - 1 ? gx : WW - 1;
            cpasync16p(abuf + pix * 144 + q * 16,
                       asrc + ((size_t)gyc * 128 + gxc) * 128 + q * 16, ok);
        }
    };
    auto issueB = [&](int it2) {
        int c2 = it2 >> ntsh, ti2 = it2 & (nt - 1);
        const char* bsrc = (const char*)g_wbs_up + (size_t)(tapid[ti2] * 8 + c2) * 24576;
        uint32_t bbuf = sbase + U_B0 + (it2 % 3) * U_BBUF;
#pragma unroll
        for (int i = 0; i < 3; i++) {
            int e = tid + i * 512;
            int row = e >> 3, q = e & 7;
            cpasync16(bbuf + row * 144 + q * 16, bsrc + row * 128 + q * 16);
        }
    };

    float acc[2][6][4];
#pragma unroll
    for (int mi = 0; mi < 2; mi++)
#pragma unroll
        for (int ni = 0; ni < 6; ni++)
#pragma unroll
            for (int q = 0; q < 4; q++) acc[mi][ni][q] = 0.f;

    issueA(0); CP_COMMIT();
    issueB(0); CP_COMMIT();
    issueA(1); CP_COMMIT();
    issueB(1); CP_COMMIT();

    for (int it = 0; it < NIT; it++) {
        int c = it >> ntsh, ti = it & (nt - 1);
        CP_WAIT2();
        __syncthreads();

        if (ti == 0 && c + 2 < 8) issueA(c + 2);
        CP_COMMIT();
        if (it + 2 < NIT) issueB(it + 2);
        CP_COMMIT();

        uint32_t sA = sbase + (c % 3) * U_ABUF;
        uint32_t sB = sbase + U_B0 + (it % 3) * U_BBUF;
        int ap0 = ((wm * 2 + 0) * 17 + rowsel + pixoff[ti]) * 144;
        int ap1 = ((wm * 2 + 1) * 17 + rowsel + pixoff[ti]) * 144;
#pragma unroll
        for (int kk = 0; kk < 6; kk++) {
            int akoff = (AKo[kk] + ksel * 8) * 2;
            int bkoff = (BKo[kk] + ksel * 8) * 2;
            uint32_t ar[2][4];
            ldsm_x4(ar[0], sA + ap0 + akoff);
            ldsm_x4(ar[1], sA + ap1 + akoff);
            uint32_t br[3][4];
#pragma unroll
            for (int nj = 0; nj < 3; nj++)
                ldsm_x4(br[nj], sB + (wn * 48 + nj * 16 + rowsel) * 144 + bkoff);
#pragma unroll
            for (int mi = 0; mi < 2; mi++)
#pragma unroll
                for (int ni = 0; ni < 6; ni++) {
                    int nj = ni >> 1, pr = ni & 1;
                    mma16816(acc[mi][ni], ar[mi], br[nj][pr], br[nj][pr + 2]);
                }
        }
        // trailing barrier elided: start barrier of it+1 orders buffer reuse
    }

    CP_WAIT0();
    __syncthreads();

    float* smf = (float*)smem;
#pragma unroll
    for (int mi = 0; mi < 2; mi++)
#pragma unroll
        for (int ni = 0; ni < 6; ni++) {
            int m = wm * 32 + mi * 16 + (lane >> 2);
            int col = wn * 48 + ni * 8 + (lane & 3) * 2;
            smf[m * U_EPIP + col] = acc[mi][ni][0];
            smf[m * U_EPIP + col + 1] = acc[mi][ni][1];
            smf[(m + 8) * U_EPIP + col] = acc[mi][ni][2];
            smf[(m + 8) * U_EPIP + col + 1] = acc[mi][ni][3];
        }
    __syncthreads();

    {
        int px = tid & 127;
        int ocl = tid >> 7;
        int my = px >> 4, mx = px & 15;
        int oy = 2 * (y0 + my) + (cls >> 1);
        int ox = 2 * (x0 + mx) + (cls & 1);
        float nz = (*ns1p) * noise1[(size_t)n * OH * OW + oy * OW + ox];
        const float* isgp = g_isg_up + n * CM;
        const float* scv = g_s_cv + n * CM;
#pragma unroll 4
        for (int ob = 0; ob < 48; ob++) {
            int oc = ob * 4 + ocl;
            float d = smf[px * U_EPIP + oc];
            float val = fmaf(d, isgp[oc], b_up[oc]) + nz;
            val = (val > 0.f ? val : 0.2f * val) * scv[oc];
            smf[px * U_EPIP + oc] = val;
        }
    }
    __syncthreads();

    {
        uint32_t* gbase = (uint32_t*)g_hs + (size_t)n * 6 * 65536 * 32;
        for (int e = tid; e < 6144; e += 512) {
            int q = e & 7;
            int pxc = e >> 3;
            int px = pxc & 127;
            int cc = pxc >> 7;
            int my = px >> 4, mx = px & 15;
            int pxg = (2 * (y0 + my) + (cls >> 1)) * OW + 2 * (x0 + mx) + (cls & 1);
            int r = q >> 2;
            int pp0 = (q & 3) << 2;
            const float* sp = smf + px * U_EPIP + cc * 32 + 2 * pp0;
            uint32_t w[4];
#pragma unroll
            for (int j = 0; j < 4; j++) {
                uint32_t hiP, loP;
                split2(sp[2 * j], sp[2 * j + 1], hiP, loP);
                w[j] = (r == 1) ? loP : hiP;
            }
            *(uint4*)(gbase + ((size_t)cc * 65536 + pxg) * 32 + q * 4) =
                make_uint4(w[0], w[1], w[2], w[3]);
        }
    }
}

// ---------------------------------------------------------------------------
// Conv2 + to-RGB fused: M=128 px tile, 512 thr, 4m x 4n (tile 32x32).
// TWO TAPS PER ITERATION (27 iters). A prefetch issued at the FIRST iteration
// fully inside a chunk (t0==0 or t0==1) — never while the victim ring buffer
// is being read (fixes R16 race).
// ---------------------------------------------------------------------------
#define C_ABUF (180 * 144)
#define C_BBUF (256 * 144)                     // 2 taps per buffer
#define C_B0   (3 * C_ABUF)                    // 77760
#define C_CF   (3 * C_ABUF + 3 * C_BBUF)       // 188352
#define C_SMEM (C_CF + 3 * CO * 4)             // 189888
#define EPIP 133

__global__ __launch_bounds__(512, 1) void k_conv2_mma(
    const float* __restrict__ noise2, const float* __restrict__ b_conv,
    const float* __restrict__ ns2p, const float* __restrict__ y,
    const float* __restrict__ w_rgb, const float* __restrict__ b_rgb,
    float* __restrict__ out, float* __restrict__ yout) {
    extern __shared__ __align__(16) char smem[];
    uint32_t sbase = smem_u32(smem);
    float* cf = (float*)(smem + C_CF);

    int tid = threadIdx.x;
    int wid = tid >> 5, lane = tid & 31;
    int wm = wid & 3, wn = wid >> 2;
    int n = blockIdx.z;
    int y0 = blockIdx.y * 8, x0 = blockIdx.x * 16;

    if (tid < CO) {
        float s = g_s_rgb[n * CO + tid];
#pragma unroll
        for (int c = 0; c < 3; c++) cf[c * CO + tid] = w_rgb[c * CO + tid] * s;
    }

    int rowsel = lane & 15, ksel = lane >> 4;

    auto issueA = [&](int cc) {
        const char* asrc = (const char*)g_hs + ((size_t)(n * 6 + cc) * 65536) * 128;
        uint32_t abuf = sbase + (cc % 3) * C_ABUF;
        for (int e = tid; e < 1440; e += 512) {
            int pix = e >> 3, q = e & 7;
            int ry = pix / 18, rx = pix % 18;
            int gy = y0 - 1 + ry, gx = x0 - 1 + rx;
            uint32_t ok = ((unsigned)gy < (unsigned)OH && (unsigned)gx < (unsigned)OW)
                              ? 16u : 0u;
            int gyc = gy < 0 ? 0 : (gy > OH - 1 ? OH - 1 : gy);
            int gxc = gx < 0 ? 0 : (gx > OW - 1 ? OW - 1 : gx);
            cpasync16p(abuf + pix * 144 + q * 16,
                       asrc + ((size_t)gyc * 256 + gxc) * 128 + q * 16, ok);
        }
    };
    // B: two contiguous taps (global taps 2j, 2j+1), 256 rows.
    auto issueB2 = [&](int j2) {
        const char* bsrc = (const char*)g_wbs + (size_t)(2 * j2) * 16384;
        uint32_t bbuf = sbase + C_B0 + (j2 % 3) * C_BBUF;
#pragma unroll
        for (int i = 0; i < 4; i++) {
            int e = tid + i * 512;
            int row = e >> 3, q = e & 7;
            cpasync16(bbuf + row * 144 + q * 16, bsrc + row * 128 + q * 16);
        }
    };

    float acc[2][4][4];
#pragma unroll
    for (int mi = 0; mi < 2; mi++)
#pragma unroll
        for (int ni = 0; ni < 4; ni++)
#pragma unroll
            for (int q = 0; q < 4; q++) acc[mi][ni][q] = 0.f;

    issueA(0); CP_COMMIT();
    issueB2(0); CP_COMMIT();
    issueA(1); CP_COMMIT();
    issueB2(1); CP_COMMIT();

    // (c0,t0) advances by 2 taps per iteration; t0 cycles 0,2,4,6,8,1,3,5,7.
    int c0 = 0, t0 = 0;
    for (int j = 0; j < 27; j++) {
        int t1 = t0 + 1, c1 = c0;
        if (t1 == 9) { t1 = 0; c1 = c0 + 1; }

        CP_WAIT2();
        __syncthreads();

        // A prefetch at the FIRST iteration fully inside chunk c0 (t0 in {0,1}):
        // victim buffer (c0+2)%3 holds chunk c0-1, last read last iteration,
        // ordered by the start barrier above. Needed >=4 iterations later.
        if (t0 <= 1 && c0 + 2 < 6) issueA(c0 + 2);
        CP_COMMIT();
        if (j + 2 < 27) issueB2(j + 2);
        CP_COMMIT();

        uint32_t sB = sbase + C_B0 + (j % 3) * C_BBUF;
#pragma unroll
        for (int st = 0; st < 2; st++) {
            int cc = st ? c1 : c0;
            int tt = st ? t1 : t0;
            uint32_t sA = sbase + (cc % 3) * C_ABUF;
            int ky = tt / 3, kx = tt % 3;
            int ap0 = ((ky + wm * 2 + 0) * 18 + kx + rowsel) * 144;
            int ap1 = ((ky + wm * 2 + 1) * 18 + kx + rowsel) * 144;
            uint32_t sBt = sB + st * (128 * 144);
#pragma unroll
            for (int kk = 0; kk < 6; kk++) {
                int akoff = (AKo[kk] + ksel * 8) * 2;
                int bkoff = (BKo[kk] + ksel * 8) * 2;
                uint32_t ar[2][4];
                ldsm_x4(ar[0], sA + ap0 + akoff);
                ldsm_x4(ar[1], sA + ap1 + akoff);
                uint32_t br[2][4];
#pragma unroll
                for (int nj = 0; nj < 2; nj++)
                    ldsm_x4(br[nj], sBt + (wn * 32 + nj * 16 + rowsel) * 144 + bkoff);
#pragma unroll
                for (int mi = 0; mi < 2; mi++)
#pragma unroll
                    for (int ni = 0; ni < 4; ni++) {
                        int nj = ni >> 1, pr = ni & 1;
                        mma16816(acc[mi][ni], ar[mi], br[nj][pr], br[nj][pr + 2]);
                    }
            }
        }
        // trailing barrier elided: start barrier of j+1 orders buffer reuse
        t0 += 2;
        if (t0 >= 9) { t0 -= 9; c0++; }
    }

    CP_WAIT0();
    __syncthreads();

    float* smf = (float*)smem;
#pragma unroll
    for (int mi = 0; mi < 2; mi++)
#pragma unroll
        for (int ni = 0; ni < 4; ni++) {
            int m = wm * 32 + mi * 16 + (lane >> 2);
            int col = wn * 32 + ni * 8 + (lane & 3) * 2;
            smf[m * EPIP + col] = acc[mi][ni][0];
            smf[m * EPIP + col + 1] = acc[mi][ni][1];
            smf[(m + 8) * EPIP + col] = acc[mi][ni][2];
            smf[(m + 8) * EPIP + col + 1] = acc[mi][ni][3];
        }
    __syncthreads();

    {
        int px = tid & 127;
        int ocl = tid >> 7;
        int my = px >> 4, mx = px & 15;
        int yy = y0 + my, xx = x0 + mx;
        float nz = (*ns2p) * noise2[(n * OH + yy) * OW + xx];
        const float* isgp = g_isg_cv + n * CO;
#pragma unroll 4
        for (int ob = 0; ob < 32; ob++) {
            int oc = ob * 4 + ocl;
            float d = smf[px * EPIP + oc];
            float val = fmaf(d, isgp[oc], b_conv[oc]) + nz;
            val = val > 0.f ? val : 0.2f * val;
            smf[px * EPIP + oc] = val;
            out[(((size_t)n * CO + oc) * OH + yy) * OW + xx] = val;
        }
    }
    __syncthreads();

    if (tid < 128) {
        int px = tid;
        int my = px >> 4, mx = px & 15;
        int oy = y0 + my, ox = x0 + mx;
        float a0 = b_rgb[0], a1 = b_rgb[1], a2 = b_rgb[2];
        const float* sp = smf + px * EPIP;
#pragma unroll 4
        for (int oc = 0; oc < CO; oc++) {
            float hv = sp[oc];
            a0 = fmaf(hv, cf[oc], a0);
            a1 = fmaf(hv, cf[CO + oc], a1);
            a2 = fmaf(hv, cf[2 * CO + oc], a2);
        }
        a0 = a0 > 0.f ? a0 : 0.2f * a0;
        a1 = a1 > 0.f ? a1 : 0.2f * a1;
        a2 = a2 > 0.f ? a2 : 0.2f * a2;
        float rr[3] = {a0, a1, a2};

        float fy = 0.5f * oy - 0.25f;
        int iyf = (int)floorf(fy);
        float wy = fy - (float)iyf;
        int iy0 = iyf < 0 ? 0 : iyf;
        int iy1 = (iyf + 1) > (HH - 1) ? (HH - 1) : (iyf + 1);
        float fx = 0.5f * ox - 0.25f;
        int ixf = (int)floorf(fx);
        float wx = fx - (float)ixf;
        int ix0 = ixf < 0 ? 0 : ixf;
        int ix1 = (ixf + 1) > (WW - 1) ? (WW - 1) : (ixf + 1);

#pragma unroll
        for (int ch = 0; ch < 3; ch++) {
            const float* yp = y + ((size_t)(n * 3 + ch) * HH) * WW;
            float v00 = yp[iy0 * WW + ix0], v01 = yp[iy0 * WW + ix1];
            float v10 = yp[iy1 * WW + ix0], v11 = yp[iy1 * WW + ix1];
            float vt = v00 + (v01 - v00) * wx;
            float vb = v10 + (v11 - v10) * wx;
            float val = vt + (vb - vt) * wy;
            yout[(((size_t)n * 3 + ch) * OH + oy) * OW + ox] = val + rr[ch];
        }
    }
}

// ---------------------------------------------------------------------------
extern "C" void kernel_launch(void* const* d_in, const int* in_sizes, int n_in,
                              void* d_out, int out_size) {
    const float* x       = (const float*)d_in[0];
    const float* v       = (const float*)d_in[1];
    const float* y       = (const float*)d_in[2];
    const float* noise1  = (const float*)d_in[3];
    const float* noise2  = (const float*)d_in[4];
    const float* w_up    = (const float*)d_in[5];
    const float* b_up    = (const float*)d_in[6];
    const float* sw_up   = (const float*)d_in[7];
    const float* sb_up   = (const float*)d_in[8];
    const float* w_conv  = (const float*)d_in[9];
    const float* b_conv  = (const float*)d_in[10];
    const float* sw_conv = (const float*)d_in[11];
    const float* sb_conv = (const float*)d_in[12];
    const float* w_rgb   = (const float*)d_in[13];
    const float* b_rgb   = (const float*)d_in[14];
    const float* sw_rgb  = (const float*)d_in[15];
    const float* sb_rgb  = (const float*)d_in[16];
    const float* ns1     = (const float*)d_in[17];
    const float* ns2     = (const float*)d_in[18];
    float* out = (float*)d_out;

    (void)in_sizes; (void)n_in; (void)out_size;

    k_prep_w<<<(9 * 8 * CM * 64 + 255) / 256, 256>>>(w_up, w_conv);

    dim3 gst(72, NB);
    k_style_all<<<gst, 256>>>(v, sw_up, sb_up, sw_conv, sb_conv, sw_rgb, sb_rgb);

    dim3 gsg(80, NB);
    k_sigma_all<<<gsg, 128>>>();

    dim3 gxs(128, 8, NB);
    k_xsplit<<<gxs, 256>>>(x);

    cudaFuncSetAttribute(k_upconv_mma, cudaFuncAttributeMaxDynamicSharedMemorySize,
                         U_SMEM);
    dim3 gup(8, 16, NB * 4);
    k_upconv_mma<<<gup, 512, U_SMEM>>>(noise1, b_up, ns1);

    cudaFuncSetAttribute(k_conv2_mma, cudaFuncAttributeMaxDynamicSharedMemorySize,
                         C_SMEM);
    dim3 gcv(16, 32, NB);
    k_conv2_mma<<<gcv, 512, C_SMEM>>>(noise2, b_conv, ns2, y, w_rgb, b_rgb,
                                      out, out + (size_t)NB * CO * OH * OW);
}